// round 8
// baseline (speedup 1.0000x reference)
#include <cuda_runtime.h>
#include <math.h>

typedef unsigned long long u64;

// ---------------- pretransposed weights (device scratch) ----------------
__device__ float g_WqT[16384];   // [c][j] = Wq[j][c] * 1/sqrt(32)
__device__ float g_WvT[16384];   // [c][j] = Wv[j][c]
__device__ float g_WoP[16384];   // [j][oc] = Wo[oc][(j&31)*4 + (j>>5)]  (permute folded)
__device__ float g_Se1T[4096];   // [oc][i] = Wse1[i][oc]
__device__ float g_Se2T[4096];   // [i][oc] = Wse2[oc][i]
__device__ float g_bqs[128];     // bq * 1/sqrt(32)

#define SCALE 0.17677669529663687f

__global__ void k_pre(const float* __restrict__ Wq, const float* __restrict__ bq,
                      const float* __restrict__ Wv, const float* __restrict__ Wo,
                      const float* __restrict__ Wse1, const float* __restrict__ Wse2)
{
    int i = blockIdx.x * 256 + threadIdx.x;
    if (i < 16384) {
        int a = i >> 7, b = i & 127;
        g_WqT[i] = Wq[b*128 + a] * SCALE;      // WqT[c][j]
        g_WvT[i] = Wv[b*128 + a];              // WvT[c][j]
        int j = a, oc = b;
        g_WoP[i] = Wo[oc*128 + ((j & 31)*4 + (j >> 5))];
    }
    if (i < 4096) {
        int oc1 = i >> 5, i1 = i & 31;
        g_Se1T[i] = Wse1[i1*128 + oc1];
        int i2 = i >> 7, oc2 = i & 127;
        g_Se2T[i] = Wse2[oc2*32 + i2];
    }
    if (i < 128) g_bqs[i] = bq[i] * SCALE;
}

// ---------------- helpers ----------------
__device__ __forceinline__ u64 pk2(float lo, float hi) {
    u64 r; asm("mov.b64 %0, {%1, %2};" : "=l"(r) : "f"(lo), "f"(hi)); return r;
}
__device__ __forceinline__ void upk(u64 v, float& lo, float& hi) {
    asm("mov.b64 {%0, %1}, %2;" : "=f"(lo), "=f"(hi) : "l"(v));
}
__device__ __forceinline__ u64 fma2(u64 a, u64 b, u64 c) {
    u64 d; asm("fma.rn.f32x2 %0, %1, %2, %3;" : "=l"(d) : "l"(a), "l"(b), "l"(c)); return d;
}
__device__ __forceinline__ void cpa16(unsigned dst, const void* src) {
    asm volatile("cp.async.cg.shared.global [%0], [%1], 16;" :: "r"(dst), "l"(src));
}
__device__ __forceinline__ void cp_commit() { asm volatile("cp.async.commit_group;"); }
__device__ __forceinline__ void cp_waitall() { asm volatile("cp.async.wait_group 0;" ::: "memory"); }
__device__ __forceinline__ float sigm(float z) { return 1.0f / (1.0f + __expf(-z)); }

// ---------------- smem layout (floats), 32 rows/block ----------------
#define W1   0        // 16384: WqT -> WvT -> [Se1T | Se2T@+4096 | Wg@+8192]
#define W2   16384    // 16384: Wk (natural [j][c]) -> WoP
#define CTX  32768    // 17408: qT[128][34]@+0 -> qk[32][512] -> ctxT[(h*128+c)][34]
#define OT   (CTX + 13056)   // oT[j][34] (over ctxT tail)
#define O2T  (CTX + 0)       // o2T[oc][34] (over ctxT head)
#define XT   50176    // 4352: xT[128][34]
#define SS   54528    // 2560: scores[row][n][4h] -> T1T[i][34]
#define GG   57088    // 32 gates
#define SMEM_FLOATS 57120    // 228480 B

__global__ void __launch_bounds__(512, 1) k_fused(
    const float* __restrict__ x,
    const float* __restrict__ nb,
    const float* __restrict__ Wk,
    const float* __restrict__ bv, const float* __restrict__ bo,
    const float* __restrict__ Wg, const float* __restrict__ bg,
    float* __restrict__ out)
{
    extern __shared__ float sm[];
    const int t = threadIdx.x;
    const int lane = t & 31;
    const int w = t >> 5;               // warp 0..15
    const int jl = lane & 7;            // j-lane (8)
    const int rg = lane >> 3;           // row-group (4)
    const int qg = w & 3;               // quadrant (j/oc/head)
    const int rq = w >> 2;              // row-quarter
    const int jbase = qg*32 + jl*4;     // j/oc quad base
    const int rpos = rq*8 + rg*2;       // row pair position
    const long rowBase = (long)blockIdx.x * 32;
    unsigned sb = (unsigned)__cvta_generic_to_shared(sm);

    // ============ phase 0: WqT->W1, Wk->W2 (cp.async); build xT ============
    #pragma unroll
    for (int i = t; i < 4096; i += 512) cpa16(sb + W1*4 + i*16, g_WqT + i*4);
    #pragma unroll
    for (int i = t; i < 4096; i += 512) cpa16(sb + W2*4 + i*16, Wk + i*4);
    cp_commit();
    {
        const float4* xg = (const float4*)x + rowBase*32;
        #pragma unroll
        for (int it = 0; it < 2; it++) {
            int idx = t + 512*it;
            int r = idx >> 5, c4 = idx & 31;
            float4 v = xg[idx];
            sm[XT + (c4*4+0)*34 + r] = v.x;
            sm[XT + (c4*4+1)*34 + r] = v.y;
            sm[XT + (c4*4+2)*34 + r] = v.z;
            sm[XT + (c4*4+3)*34 + r] = v.w;
        }
    }
    cp_waitall();
    __syncthreads();

    // ============ stage A: q = s*(Wq x + bq) -> qT[j][34] ============
    {
        u64 a0, a1, a2, a3;
        { float b0 = g_bqs[jbase], b1 = g_bqs[jbase+1],
                b2 = g_bqs[jbase+2], b3 = g_bqs[jbase+3];
          a0 = pk2(b0,b0); a1 = pk2(b1,b1); a2 = pk2(b2,b2); a3 = pk2(b3,b3); }
        #pragma unroll 4
        for (int c = 0; c < 128; c++) {
            float4 wv = *(const float4*)&sm[W1 + c*128 + jbase];
            u64 xp = *(const u64*)&sm[XT + c*34 + rpos];
            a0 = fma2(pk2(wv.x,wv.x), xp, a0);
            a1 = fma2(pk2(wv.y,wv.y), xp, a1);
            a2 = fma2(pk2(wv.z,wv.z), xp, a2);
            a3 = fma2(pk2(wv.w,wv.w), xp, a3);
        }
        *(u64*)&sm[CTX + (jbase+0)*34 + rpos] = a0;
        *(u64*)&sm[CTX + (jbase+1)*34 + rpos] = a1;
        *(u64*)&sm[CTX + (jbase+2)*34 + rpos] = a2;
        *(u64*)&sm[CTX + (jbase+3)*34 + rpos] = a3;
    }
    __syncthreads();
    // W1 free -> prefetch WvT
    #pragma unroll
    for (int i = t; i < 4096; i += 512) cpa16(sb + W1*4 + i*16, g_WvT + i*4);
    cp_commit();

    // ============ stage B: qk[row][h*128+c] = sum_d q[row][h*32+d]*Wk[h*32+d][c] ============
    {
        u64 acc[4][4];                        // [cc][cq]
        #pragma unroll
        for (int cc = 0; cc < 4; cc++)
            #pragma unroll
            for (int q = 0; q < 4; q++) acc[cc][q] = 0ull;
        #pragma unroll 4
        for (int d = 0; d < 32; d++) {
            const int j = qg*32 + d;          // head = qg
            u64 qp = *(const u64*)&sm[CTX + j*34 + rpos];
            #pragma unroll
            for (int cc = 0; cc < 4; cc++) {
                float4 wv = *(const float4*)&sm[W2 + j*128 + cc*32 + jl*4];
                acc[cc][0] = fma2(pk2(wv.x,wv.x), qp, acc[cc][0]);
                acc[cc][1] = fma2(pk2(wv.y,wv.y), qp, acc[cc][1]);
                acc[cc][2] = fma2(pk2(wv.z,wv.z), qp, acc[cc][2]);
                acc[cc][3] = fma2(pk2(wv.w,wv.w), qp, acc[cc][3]);
            }
        }
        __syncthreads();      // all qT reads drained before qk overwrites region
        #pragma unroll
        for (int rr = 0; rr < 2; rr++) {
            #pragma unroll
            for (int cc = 0; cc < 4; cc++) {
                float4 o; float lo, hi;
                upk(acc[cc][0], lo, hi); o.x = rr ? hi : lo;
                upk(acc[cc][1], lo, hi); o.y = rr ? hi : lo;
                upk(acc[cc][2], lo, hi); o.z = rr ? hi : lo;
                upk(acc[cc][3], lo, hi); o.w = rr ? hi : lo;
                *(float4*)&sm[CTX + (rpos+rr)*512 + qg*128 + cc*32 + jl*4] = o;
            }
        }
    }
    __syncthreads();
    // W2 free -> prefetch WoP
    #pragma unroll
    for (int i = t; i < 4096; i += 512) cpa16(sb + W2*4 + i*16, g_WoP + i*4);
    cp_commit();

    // ============ stage C1: scores ============
    for (int idx = t; idx < 640; idx += 512) {
        const int row = idx / 20;
        const int n = idx - row*20;
        const float4* nbp = (const float4*)(nb + (((rowBase + row)*20 + n) << 7));
        float a0 = 0.f, a1 = 0.f, a2 = 0.f, a3 = 0.f;
        #pragma unroll 8
        for (int c4 = 0; c4 < 32; c4++) {
            float4 v = nbp[c4];
            float4 h0 = *(const float4*)&sm[CTX + row*512 +   0 + c4*4];
            float4 h1 = *(const float4*)&sm[CTX + row*512 + 128 + c4*4];
            float4 h2 = *(const float4*)&sm[CTX + row*512 + 256 + c4*4];
            float4 h3 = *(const float4*)&sm[CTX + row*512 + 384 + c4*4];
            a0 += h0.x*v.x + h0.y*v.y + h0.z*v.z + h0.w*v.w;
            a1 += h1.x*v.x + h1.y*v.y + h1.z*v.z + h1.w*v.w;
            a2 += h2.x*v.x + h2.y*v.y + h2.z*v.z + h2.w*v.w;
            a3 += h3.x*v.x + h3.y*v.y + h3.z*v.z + h3.w*v.w;
        }
        *(float4*)&sm[SS + idx*4] = make_float4(a0, a1, a2, a3);
    }
    __syncthreads();

    // ============ stage C2: softmax over n ============
    if (t < 128) {
        const int row = t >> 2, h = t & 3;
        const int base = SS + row*80 + h;
        float m = -1e30f;
        float s[20];
        #pragma unroll
        for (int n = 0; n < 20; n++) { s[n] = sm[base + n*4]; m = fmaxf(m, s[n]); }
        float tot = 0.f;
        #pragma unroll
        for (int n = 0; n < 20; n++) { s[n] = __expf(s[n] - m); tot += s[n]; }
        float inv = 1.0f / tot;
        #pragma unroll
        for (int n = 0; n < 20; n++) sm[base + n*4] = s[n] * inv;
    }
    __syncthreads();

    // ============ stage C3: ctxT[(h*128+c)][row] ============
    {
        const int cq = w & 3, rq3 = w >> 2;
        const int c = cq*32 + lane;
        u64 cacc[8][2];
        #pragma unroll
        for (int r = 0; r < 8; r++) { cacc[r][0] = 0ull; cacc[r][1] = 0ull; }
        #pragma unroll
        for (int r = 0; r < 8; r++) {
            const int row = rq3*8 + r;
            const float* nbr = nb + ((rowBase + row)*20 << 7) + c;
            #pragma unroll 4
            for (int n = 0; n < 20; n++) {
                float v = __ldg(nbr + n*128);
                u64 vp = pk2(v, v);
                float4 at = *(const float4*)&sm[SS + row*80 + n*4];
                cacc[r][0] = fma2(pk2(at.x, at.y), vp, cacc[r][0]);
                cacc[r][1] = fma2(pk2(at.z, at.w), vp, cacc[r][1]);
            }
        }
        __syncthreads();   // qk fully consumed before ctxT overwrites region
        #pragma unroll
        for (int r = 0; r < 8; r++) {
            const int row = rq3*8 + r;
            float v0, v1, v2, v3;
            upk(cacc[r][0], v0, v1);
            upk(cacc[r][1], v2, v3);
            sm[CTX + (0*128 + c)*34 + row] = v0;
            sm[CTX + (1*128 + c)*34 + row] = v1;
            sm[CTX + (2*128 + c)*34 + row] = v2;
            sm[CTX + (3*128 + c)*34 + row] = v3;
        }
    }
    cp_waitall();          // WvT / WoP landed
    __syncthreads();

    // ============ stage D: o = Wv ctx + bv -> oT[j][34] (head = qg) ============
    {
        u64 a0, a1, a2, a3;
        { float b0 = __ldg(&bv[jbase]),   b1 = __ldg(&bv[jbase+1]),
                b2 = __ldg(&bv[jbase+2]), b3 = __ldg(&bv[jbase+3]);
          a0 = pk2(b0,b0); a1 = pk2(b1,b1); a2 = pk2(b2,b2); a3 = pk2(b3,b3); }
        #pragma unroll 4
        for (int c = 0; c < 128; c++) {
            float4 wv = *(const float4*)&sm[W1 + c*128 + jbase];
            u64 cp = *(const u64*)&sm[CTX + (qg*128 + c)*34 + rpos];
            a0 = fma2(pk2(wv.x,wv.x), cp, a0);
            a1 = fma2(pk2(wv.y,wv.y), cp, a1);
            a2 = fma2(pk2(wv.z,wv.z), cp, a2);
            a3 = fma2(pk2(wv.w,wv.w), cp, a3);
        }
        __syncthreads();   // all ctxT reads done before oT overwrites tail
        *(u64*)&sm[OT + (jbase+0)*34 + rpos] = a0;
        *(u64*)&sm[OT + (jbase+1)*34 + rpos] = a1;
        *(u64*)&sm[OT + (jbase+2)*34 + rpos] = a2;
        *(u64*)&sm[OT + (jbase+3)*34 + rpos] = a3;
    }
    // W1 free -> prefetch SE weights
    #pragma unroll
    for (int i = t; i < 1024; i += 512) cpa16(sb + W1*4 + i*16, g_Se1T + i*4);
    #pragma unroll
    for (int i = t; i < 1024; i += 512) cpa16(sb + (W1+4096)*4 + i*16, g_Se2T + i*4);
    if (t < 64) cpa16(sb + (W1+8192)*4 + t*16, Wg + t*4);
    cp_commit();
    __syncthreads();       // oT visible

    // ============ stage E: o2 = WoP . o + bo -> o2T[oc][34] ============
    {
        u64 a0, a1, a2, a3;
        { float b0 = __ldg(&bo[jbase]),   b1 = __ldg(&bo[jbase+1]),
                b2 = __ldg(&bo[jbase+2]), b3 = __ldg(&bo[jbase+3]);
          a0 = pk2(b0,b0); a1 = pk2(b1,b1); a2 = pk2(b2,b2); a3 = pk2(b3,b3); }
        #pragma unroll 4
        for (int j = 0; j < 128; j++) {
            float4 wv = *(const float4*)&sm[W2 + j*128 + jbase];
            u64 op = *(const u64*)&sm[OT + j*34 + rpos];
            a0 = fma2(pk2(wv.x,wv.x), op, a0);
            a1 = fma2(pk2(wv.y,wv.y), op, a1);
            a2 = fma2(pk2(wv.z,wv.z), op, a2);
            a3 = fma2(pk2(wv.w,wv.w), op, a3);
        }
        // o2T region (ctxT head) disjoint from oT (tail): no hazard
        *(u64*)&sm[O2T + (jbase+0)*34 + rpos] = a0;
        *(u64*)&sm[O2T + (jbase+1)*34 + rpos] = a1;
        *(u64*)&sm[O2T + (jbase+2)*34 + rpos] = a2;
        *(u64*)&sm[O2T + (jbase+3)*34 + rpos] = a3;
    }
    cp_waitall();          // SE weights landed
    __syncthreads();

    // ============ stage F: T1 = relu(Se1 . o2) -> T1T[i][34]  (4 warps) ============
    if (w < 4) {
        const int fr = w*8 + rg*2;             // row pair
        u64 a0 = 0ull, a1 = 0ull, a2 = 0ull, a3 = 0ull;
        #pragma unroll 4
        for (int oc = 0; oc < 128; oc++) {
            float4 wv = *(const float4*)&sm[W1 + oc*32 + jl*4];
            u64 op = *(const u64*)&sm[O2T + oc*34 + fr];
            a0 = fma2(pk2(wv.x,wv.x), op, a0);
            a1 = fma2(pk2(wv.y,wv.y), op, a1);
            a2 = fma2(pk2(wv.z,wv.z), op, a2);
            a3 = fma2(pk2(wv.w,wv.w), op, a3);
        }
        float lo, hi;
        upk(a0, lo, hi); *(u64*)&sm[SS + (jl*4+0)*34 + fr] = pk2(fmaxf(lo,0.f), fmaxf(hi,0.f));
        upk(a1, lo, hi); *(u64*)&sm[SS + (jl*4+1)*34 + fr] = pk2(fmaxf(lo,0.f), fmaxf(hi,0.f));
        upk(a2, lo, hi); *(u64*)&sm[SS + (jl*4+2)*34 + fr] = pk2(fmaxf(lo,0.f), fmaxf(hi,0.f));
        upk(a3, lo, hi); *(u64*)&sm[SS + (jl*4+3)*34 + fr] = pk2(fmaxf(lo,0.f), fmaxf(hi,0.f));
    }
    __syncthreads();

    // ============ stage G: o2 *= sigmoid(Se2 . T1) ============
    {
        u64 a0 = 0ull, a1 = 0ull, a2 = 0ull, a3 = 0ull;
        #pragma unroll 4
        for (int i = 0; i < 32; i++) {
            float4 wv = *(const float4*)&sm[W1 + 4096 + i*128 + jbase];
            u64 tp = *(const u64*)&sm[SS + i*34 + rpos];
            a0 = fma2(pk2(wv.x,wv.x), tp, a0);
            a1 = fma2(pk2(wv.y,wv.y), tp, a1);
            a2 = fma2(pk2(wv.z,wv.z), tp, a2);
            a3 = fma2(pk2(wv.w,wv.w), tp, a3);
        }
        u64 se[4] = {a0, a1, a2, a3};
        #pragma unroll
        for (int q = 0; q < 4; q++) {
            float lo, hi; upk(se[q], lo, hi);
            const int a = O2T + (jbase+q)*34 + rpos;
            sm[a]   *= sigm(lo);
            sm[a+1] *= sigm(hi);
        }
    }
    __syncthreads();

    // ============ stage H: residual gate ============
    {
        const float bgv = __ldg(bg);
        #pragma unroll
        for (int r2 = 0; r2 < 2; r2++) {
            const int row = 2*w + r2;
            float p = 0.0f;
            #pragma unroll
            for (int k = 0; k < 4; k++) {
                const int cx = lane + 32*k;
                p += sm[W1 + 8192 + cx]       * sm[XT  + cx*34 + row];
                p += sm[W1 + 8192 + 128 + cx] * sm[O2T + cx*34 + row];
            }
            #pragma unroll
            for (int o = 16; o; o >>= 1) p += __shfl_xor_sync(0xffffffffu, p, o);
            if (lane == 0) sm[GG + row] = sigm(p + bgv);
        }
    }
    __syncthreads();

    // ============ stage I: out = g*o3 + (1-g)*x ============
    {
        float4* og4 = (float4*)out + rowBase*32;
        #pragma unroll
        for (int it = 0; it < 2; it++) {
            const int idx = t + 512*it;
            const int r = idx >> 5, c4 = idx & 31;
            const float g = sm[GG + r];
            float4 res;
            res.x = g*sm[O2T + (c4*4+0)*34 + r] + (1.0f-g)*sm[XT + (c4*4+0)*34 + r];
            res.y = g*sm[O2T + (c4*4+1)*34 + r] + (1.0f-g)*sm[XT + (c4*4+1)*34 + r];
            res.z = g*sm[O2T + (c4*4+2)*34 + r] + (1.0f-g)*sm[XT + (c4*4+2)*34 + r];
            res.w = g*sm[O2T + (c4*4+3)*34 + r] + (1.0f-g)*sm[XT + (c4*4+3)*34 + r];
            og4[idx] = res;
        }
    }
}

// =======================================================================
extern "C" void kernel_launch(void* const* d_in, const int* in_sizes, int n_in,
                              void* d_out, int out_size)
{
    const float* x    = (const float*)d_in[0];
    const float* nb   = (const float*)d_in[1];
    const float* Wq   = (const float*)d_in[2];
    const float* bq   = (const float*)d_in[3];
    const float* Wk   = (const float*)d_in[4];
    // d_in[5] = bk : constant over n => softmax-invariant, unused
    const float* Wv   = (const float*)d_in[6];
    const float* bv   = (const float*)d_in[7];
    const float* Wo   = (const float*)d_in[8];
    const float* bo   = (const float*)d_in[9];
    const float* Wse1 = (const float*)d_in[10];
    const float* Wse2 = (const float*)d_in[11];
    const float* Wg   = (const float*)d_in[12];
    const float* bg   = (const float*)d_in[13];
    float* out = (float*)d_out;

    cudaFuncSetAttribute(k_fused, cudaFuncAttributeMaxDynamicSharedMemorySize,
                         SMEM_FLOATS * 4);

    k_pre<<<64, 256>>>(Wq, bq, Wv, Wo, Wse1, Wse2);
    k_fused<<<2048, 512, SMEM_FLOATS * 4>>>(x, nb, Wk, bv, bo, Wg, bg, out);
}

// round 9
// speedup vs baseline: 1.1306x; 1.1306x over previous
#include <cuda_runtime.h>
#include <math.h>

typedef unsigned long long u64;

// ---------------- pretransposed weights (device scratch) ----------------
__device__ float g_WqT[16384];   // [c][j] = Wq[j][c] * 1/sqrt(32)
__device__ float g_WvT[16384];   // [c][j] = Wv[j][c]
__device__ float g_WoP[16384];   // [j][oc] = Wo[oc][(j&31)*4 + (j>>5)]  (permute folded)
__device__ float g_Se1T[4096];   // [oc][i] = Wse1[i][oc]
__device__ float g_Se2T[4096];   // [i][oc] = Wse2[oc][i]
__device__ float g_bqs[128];     // bq * 1/sqrt(32)

#define SCALE 0.17677669529663687f

__global__ void k_pre(const float* __restrict__ Wq, const float* __restrict__ bq,
                      const float* __restrict__ Wv, const float* __restrict__ Wo,
                      const float* __restrict__ Wse1, const float* __restrict__ Wse2)
{
    int i = blockIdx.x * 256 + threadIdx.x;
    if (i < 16384) {
        int a = i >> 7, b = i & 127;
        g_WqT[i] = Wq[b*128 + a] * SCALE;      // WqT[c][j]
        g_WvT[i] = Wv[b*128 + a];              // WvT[c][j]
        int j = a, oc = b;
        g_WoP[i] = Wo[oc*128 + ((j & 31)*4 + (j >> 5))];
    }
    if (i < 4096) {
        int oc1 = i >> 5, i1 = i & 31;
        g_Se1T[i] = Wse1[i1*128 + oc1];
        int i2 = i >> 7, oc2 = i & 127;
        g_Se2T[i] = Wse2[oc2*32 + i2];
    }
    if (i < 128) g_bqs[i] = bq[i] * SCALE;
}

// ---------------- helpers ----------------
__device__ __forceinline__ u64 pk2(float lo, float hi) {
    u64 r; asm("mov.b64 %0, {%1, %2};" : "=l"(r) : "f"(lo), "f"(hi)); return r;
}
__device__ __forceinline__ void upk(u64 v, float& lo, float& hi) {
    asm("mov.b64 {%0, %1}, %2;" : "=f"(lo), "=f"(hi) : "l"(v));
}
__device__ __forceinline__ u64 fma2(u64 a, u64 b, u64 c) {
    u64 d; asm("fma.rn.f32x2 %0, %1, %2, %3;" : "=l"(d) : "l"(a), "l"(b), "l"(c)); return d;
}
__device__ __forceinline__ u64 add2(u64 a, u64 b) {
    u64 d; asm("add.rn.f32x2 %0, %1, %2;" : "=l"(d) : "l"(a), "l"(b)); return d;
}
__device__ __forceinline__ void cpa16(unsigned dst, const void* src) {
    asm volatile("cp.async.cg.shared.global [%0], [%1], 16;" :: "r"(dst), "l"(src));
}
__device__ __forceinline__ void cp_commit() { asm volatile("cp.async.commit_group;"); }
__device__ __forceinline__ void cp_waitall() { asm volatile("cp.async.wait_group 0;" ::: "memory"); }
__device__ __forceinline__ float sigm(float z) { return 1.0f / (1.0f + __expf(-z)); }

// ---------------- smem layout (floats), 32 rows/block ----------------
#define W1   0        // 16384: WqT -> WvT -> [Se1T | Se2T@+4096 | Wg@+8192]
#define W2   16384    // 16384: Wk (natural [j][c]) -> WoP
#define CTX  32768    // 17408: qT[128][34]@0 + A-partials@+4352(3x4352)
                      //        -> qk[32][512] -> ctxT[(h*128+c)][34]
#define APART (CTX + 4352)
#define OT   (CTX + 13056)   // oT[j][34] (over ctxT tail, h=3)
#define O2T  (CTX + 0)       // o2T[oc][34] (over ctxT head)
#define XT   50176    // 4352: xT[128][34]
#define SS   54528    // 2560: scores[row][n][4h] -> T1T[i][34]
#define GG   57088    // 32 gates
#define SMEM_FLOATS 57120    // 228480 B

__global__ void __launch_bounds__(512, 1) k_fused(
    const float* __restrict__ x,
    const float* __restrict__ nb,
    const float* __restrict__ Wk,
    const float* __restrict__ bv, const float* __restrict__ bo,
    const float* __restrict__ Wg, const float* __restrict__ bg,
    float* __restrict__ out)
{
    extern __shared__ float sm[];
    const int t = threadIdx.x;
    const int lane = t & 31;
    const int w = t >> 5;               // warp 0..15
    const int jl = lane & 7;            // j-lane (8)
    const int rg = lane >> 3;           // row-group (4)
    const long rowBase = (long)blockIdx.x * 32;
    unsigned sb = (unsigned)__cvta_generic_to_shared(sm);

    // ============ phase 0: WqT->W1, Wk->W2 (cp.async); build xT ============
    #pragma unroll
    for (int i = t; i < 4096; i += 512) cpa16(sb + W1*4 + i*16, g_WqT + i*4);
    #pragma unroll
    for (int i = t; i < 4096; i += 512) cpa16(sb + W2*4 + i*16, Wk + i*4);
    cp_commit();
    {
        const float4* xg = (const float4*)x + rowBase*32;
        #pragma unroll
        for (int it = 0; it < 2; it++) {
            int idx = t + 512*it;
            int r = idx >> 5, c4 = idx & 31;
            float4 v = xg[idx];
            sm[XT + (c4*4+0)*34 + r] = v.x;
            sm[XT + (c4*4+1)*34 + r] = v.y;
            sm[XT + (c4*4+2)*34 + r] = v.z;
            sm[XT + (c4*4+3)*34 + r] = v.w;
        }
    }
    cp_waitall();
    __syncthreads();

    // ============ stage A: q = s*(Wq x + bq), split-k x4 -> qT[j][34] ============
    {
        const int qg = w & 3, ks = w >> 2;
        const int jb = qg*32 + jl*4;
        u64 acc[4][4];                       // [q][pair]
        #pragma unroll
        for (int q = 0; q < 4; q++) {
            u64 init = 0ull;
            if (ks == 0) { float b = g_bqs[jb+q]; init = pk2(b, b); }
            #pragma unroll
            for (int p = 0; p < 4; p++) acc[q][p] = init;
        }
        #pragma unroll 4
        for (int c = ks*32; c < ks*32 + 32; c++) {
            float4 wv = *(const float4*)&sm[W1 + c*128 + jb];
            u64 x0 = *(const u64*)&sm[XT + c*34 + rg*8 + 0];
            u64 x1 = *(const u64*)&sm[XT + c*34 + rg*8 + 2];
            u64 x2 = *(const u64*)&sm[XT + c*34 + rg*8 + 4];
            u64 x3 = *(const u64*)&sm[XT + c*34 + rg*8 + 6];
            u64 w0 = pk2(wv.x,wv.x), w1 = pk2(wv.y,wv.y);
            u64 w2 = pk2(wv.z,wv.z), w3 = pk2(wv.w,wv.w);
            acc[0][0]=fma2(w0,x0,acc[0][0]); acc[0][1]=fma2(w0,x1,acc[0][1]);
            acc[0][2]=fma2(w0,x2,acc[0][2]); acc[0][3]=fma2(w0,x3,acc[0][3]);
            acc[1][0]=fma2(w1,x0,acc[1][0]); acc[1][1]=fma2(w1,x1,acc[1][1]);
            acc[1][2]=fma2(w1,x2,acc[1][2]); acc[1][3]=fma2(w1,x3,acc[1][3]);
            acc[2][0]=fma2(w2,x0,acc[2][0]); acc[2][1]=fma2(w2,x1,acc[2][1]);
            acc[2][2]=fma2(w2,x2,acc[2][2]); acc[2][3]=fma2(w2,x3,acc[2][3]);
            acc[3][0]=fma2(w3,x0,acc[3][0]); acc[3][1]=fma2(w3,x1,acc[3][1]);
            acc[3][2]=fma2(w3,x2,acc[3][2]); acc[3][3]=fma2(w3,x3,acc[3][3]);
        }
        if (ks) {
            float* P = sm + APART + (ks-1)*4352;
            #pragma unroll
            for (int q = 0; q < 4; q++)
                #pragma unroll
                for (int p = 0; p < 4; p++)
                    *(u64*)&P[(jb+q)*34 + rg*8 + 2*p] = acc[q][p];
        }
        __syncthreads();
        // W1 (WqT) dead -> prefetch WvT
        #pragma unroll
        for (int i = t; i < 4096; i += 512) cpa16(sb + W1*4 + i*16, g_WvT + i*4);
        cp_commit();
        if (ks == 0) {
            #pragma unroll
            for (int pt = 0; pt < 3; pt++) {
                const float* P = sm + APART + pt*4352;
                #pragma unroll
                for (int q = 0; q < 4; q++)
                    #pragma unroll
                    for (int p = 0; p < 4; p++)
                        acc[q][p] = add2(acc[q][p], *(const u64*)&P[(jb+q)*34 + rg*8 + 2*p]);
            }
            #pragma unroll
            for (int q = 0; q < 4; q++)
                #pragma unroll
                for (int p = 0; p < 4; p++)
                    *(u64*)&sm[CTX + (jb+q)*34 + rg*8 + 2*p] = acc[q][p];
        }
    }
    __syncthreads();

    // ============ stage B: qk[row][h*128+c] = sum_d q[row][h*32+d]*Wk[h*32+d][c] ============
    {
        const int h = w & 3, cs = w >> 2;
        const int cb = cs*32 + jl*4;                  // c-quad within head
        u64 acc[4][4];
        #pragma unroll
        for (int q = 0; q < 4; q++)
            #pragma unroll
            for (int p = 0; p < 4; p++) acc[q][p] = 0ull;
        #pragma unroll 4
        for (int d = 0; d < 32; d++) {
            const int j = h*32 + d;
            float4 wv = *(const float4*)&sm[W2 + j*128 + cb];
            u64 q0 = *(const u64*)&sm[CTX + j*34 + rg*8 + 0];
            u64 q1 = *(const u64*)&sm[CTX + j*34 + rg*8 + 2];
            u64 q2 = *(const u64*)&sm[CTX + j*34 + rg*8 + 4];
            u64 q3 = *(const u64*)&sm[CTX + j*34 + rg*8 + 6];
            u64 w0 = pk2(wv.x,wv.x), w1 = pk2(wv.y,wv.y);
            u64 w2_ = pk2(wv.z,wv.z), w3 = pk2(wv.w,wv.w);
            acc[0][0]=fma2(w0,q0,acc[0][0]); acc[0][1]=fma2(w0,q1,acc[0][1]);
            acc[0][2]=fma2(w0,q2,acc[0][2]); acc[0][3]=fma2(w0,q3,acc[0][3]);
            acc[1][0]=fma2(w1,q0,acc[1][0]); acc[1][1]=fma2(w1,q1,acc[1][1]);
            acc[1][2]=fma2(w1,q2,acc[1][2]); acc[1][3]=fma2(w1,q3,acc[1][3]);
            acc[2][0]=fma2(w2_,q0,acc[2][0]); acc[2][1]=fma2(w2_,q1,acc[2][1]);
            acc[2][2]=fma2(w2_,q2,acc[2][2]); acc[2][3]=fma2(w2_,q3,acc[2][3]);
            acc[3][0]=fma2(w3,q0,acc[3][0]); acc[3][1]=fma2(w3,q1,acc[3][1]);
            acc[3][2]=fma2(w3,q2,acc[3][2]); acc[3][3]=fma2(w3,q3,acc[3][3]);
        }
        __syncthreads();        // qT reads drained before qk overwrites region
        #pragma unroll
        for (int p = 0; p < 4; p++) {
            float l0,h0,l1,h1,l2,h2,l3,h3;
            upk(acc[0][p], l0, h0); upk(acc[1][p], l1, h1);
            upk(acc[2][p], l2, h2); upk(acc[3][p], l3, h3);
            *(float4*)&sm[CTX + (rg*8+2*p  )*512 + h*128 + cb] = make_float4(l0,l1,l2,l3);
            *(float4*)&sm[CTX + (rg*8+2*p+1)*512 + h*128 + cb] = make_float4(h0,h1,h2,h3);
        }
    }
    __syncthreads();
    // W2 (Wk) dead -> prefetch WoP
    #pragma unroll
    for (int i = t; i < 4096; i += 512) cpa16(sb + W2*4 + i*16, g_WoP + i*4);
    cp_commit();

    // ============ stage C1: scores ============
    for (int idx = t; idx < 640; idx += 512) {
        const int row = idx / 20;
        const int n = idx - row*20;
        const float4* nbp = (const float4*)(nb + (((rowBase + row)*20 + n) << 7));
        float a0 = 0.f, a1 = 0.f, a2 = 0.f, a3 = 0.f;
        #pragma unroll 8
        for (int c4 = 0; c4 < 32; c4++) {
            float4 v = nbp[c4];
            float4 h0 = *(const float4*)&sm[CTX + row*512 +   0 + c4*4];
            float4 h1 = *(const float4*)&sm[CTX + row*512 + 128 + c4*4];
            float4 h2 = *(const float4*)&sm[CTX + row*512 + 256 + c4*4];
            float4 h3 = *(const float4*)&sm[CTX + row*512 + 384 + c4*4];
            a0 += h0.x*v.x + h0.y*v.y + h0.z*v.z + h0.w*v.w;
            a1 += h1.x*v.x + h1.y*v.y + h1.z*v.z + h1.w*v.w;
            a2 += h2.x*v.x + h2.y*v.y + h2.z*v.z + h2.w*v.w;
            a3 += h3.x*v.x + h3.y*v.y + h3.z*v.z + h3.w*v.w;
        }
        *(float4*)&sm[SS + idx*4] = make_float4(a0, a1, a2, a3);
    }
    __syncthreads();

    // ============ stage C2: softmax over n ============
    if (t < 128) {
        const int row = t >> 2, h = t & 3;
        const int base = SS + row*80 + h;
        float m = -1e30f;
        float s[20];
        #pragma unroll
        for (int n = 0; n < 20; n++) { s[n] = sm[base + n*4]; m = fmaxf(m, s[n]); }
        float tot = 0.f;
        #pragma unroll
        for (int n = 0; n < 20; n++) { s[n] = __expf(s[n] - m); tot += s[n]; }
        float inv = 1.0f / tot;
        #pragma unroll
        for (int n = 0; n < 20; n++) sm[base + n*4] = s[n] * inv;
    }
    __syncthreads();

    // ============ stage C3: ctxT[(h*128+c)][34] ============
    {
        const int cq = w & 3, rq3 = w >> 2;
        const int c = cq*32 + lane;
        u64 cacc[8][2];
        #pragma unroll
        for (int r = 0; r < 8; r++) { cacc[r][0] = 0ull; cacc[r][1] = 0ull; }
        #pragma unroll
        for (int r = 0; r < 8; r++) {
            const int row = rq3*8 + r;
            const float* nbr = nb + ((rowBase + row)*20 << 7) + c;
            #pragma unroll 4
            for (int n = 0; n < 20; n++) {
                float v = __ldg(nbr + n*128);
                u64 vp = pk2(v, v);
                float4 at = *(const float4*)&sm[SS + row*80 + n*4];
                cacc[r][0] = fma2(pk2(at.x, at.y), vp, cacc[r][0]);
                cacc[r][1] = fma2(pk2(at.z, at.w), vp, cacc[r][1]);
            }
        }
        __syncthreads();   // qk fully consumed before ctxT overwrites region
        #pragma unroll
        for (int r = 0; r < 8; r++) {
            const int row = rq3*8 + r;
            float v0, v1, v2, v3;
            upk(cacc[r][0], v0, v1);
            upk(cacc[r][1], v2, v3);
            sm[CTX + (0*128 + c)*34 + row] = v0;
            sm[CTX + (1*128 + c)*34 + row] = v1;
            sm[CTX + (2*128 + c)*34 + row] = v2;
            sm[CTX + (3*128 + c)*34 + row] = v3;
        }
    }
    cp_waitall();          // WvT / WoP landed
    __syncthreads();

    // ============ stage D: o = Wv ctx + bv -> oT[h*32+d][34], split-k x2 ============
    {
        const int h = w & 3, ksd = (w >> 2) & 1, rs = w >> 3;
        const int jb = h*32 + jl*4;
        const int row0 = rs*16 + rg*4;       // pairs at row0, row0+2
        u64 acc[4][2];
        #pragma unroll
        for (int q = 0; q < 4; q++) {
            u64 init = 0ull;
            if (ksd == 0) { float b = __ldg(&bv[jb+q]); init = pk2(b, b); }
            acc[q][0] = init; acc[q][1] = init;
        }
        #pragma unroll 4
        for (int c = ksd*64; c < ksd*64 + 64; c++) {
            float4 wv = *(const float4*)&sm[W1 + c*128 + jb];
            u64 a0 = *(const u64*)&sm[CTX + (h*128 + c)*34 + row0];
            u64 a1 = *(const u64*)&sm[CTX + (h*128 + c)*34 + row0 + 2];
            acc[0][0]=fma2(pk2(wv.x,wv.x),a0,acc[0][0]); acc[0][1]=fma2(pk2(wv.x,wv.x),a1,acc[0][1]);
            acc[1][0]=fma2(pk2(wv.y,wv.y),a0,acc[1][0]); acc[1][1]=fma2(pk2(wv.y,wv.y),a1,acc[1][1]);
            acc[2][0]=fma2(pk2(wv.z,wv.z),a0,acc[2][0]); acc[2][1]=fma2(pk2(wv.z,wv.z),a1,acc[2][1]);
            acc[3][0]=fma2(pk2(wv.w,wv.w),a0,acc[3][0]); acc[3][1]=fma2(pk2(wv.w,wv.w),a1,acc[3][1]);
        }
        __syncthreads();       // all ctxT reads done before oT (h=3 region) overwritten
        if (ksd == 1) {
            #pragma unroll
            for (int q = 0; q < 4; q++) {
                *(u64*)&sm[OT + (jb+q)*34 + row0]     = acc[q][0];
                *(u64*)&sm[OT + (jb+q)*34 + row0 + 2] = acc[q][1];
            }
        }
        __syncthreads();
        // W1 (WvT) dead -> prefetch SE weights
        #pragma unroll
        for (int i = t; i < 1024; i += 512) cpa16(sb + W1*4 + i*16, g_Se1T + i*4);
        #pragma unroll
        for (int i = t; i < 1024; i += 512) cpa16(sb + (W1+4096)*4 + i*16, g_Se2T + i*4);
        if (t < 64) cpa16(sb + (W1+8192)*4 + t*16, Wg + t*4);
        cp_commit();
        if (ksd == 0) {
            #pragma unroll
            for (int q = 0; q < 4; q++) {
                u64 p0 = *(const u64*)&sm[OT + (jb+q)*34 + row0];
                u64 p1 = *(const u64*)&sm[OT + (jb+q)*34 + row0 + 2];
                *(u64*)&sm[OT + (jb+q)*34 + row0]     = add2(acc[q][0], p0);
                *(u64*)&sm[OT + (jb+q)*34 + row0 + 2] = add2(acc[q][1], p1);
            }
        }
    }
    __syncthreads();

    // ============ stage E: o2 = WoP . o + bo -> o2T[oc][34], split-k x2 ============
    {
        const int qg = w & 3, kse = (w >> 2) & 1, rs = w >> 3;
        const int ob = qg*32 + jl*4;
        const int row0 = rs*16 + rg*4;
        u64 acc[4][2];
        #pragma unroll
        for (int q = 0; q < 4; q++) {
            u64 init = 0ull;
            if (kse == 0) { float b = __ldg(&bo[ob+q]); init = pk2(b, b); }
            acc[q][0] = init; acc[q][1] = init;
        }
        #pragma unroll 4
        for (int j = kse*64; j < kse*64 + 64; j++) {
            float4 wv = *(const float4*)&sm[W2 + j*128 + ob];
            u64 a0 = *(const u64*)&sm[OT + j*34 + row0];
            u64 a1 = *(const u64*)&sm[OT + j*34 + row0 + 2];
            acc[0][0]=fma2(pk2(wv.x,wv.x),a0,acc[0][0]); acc[0][1]=fma2(pk2(wv.x,wv.x),a1,acc[0][1]);
            acc[1][0]=fma2(pk2(wv.y,wv.y),a0,acc[1][0]); acc[1][1]=fma2(pk2(wv.y,wv.y),a1,acc[1][1]);
            acc[2][0]=fma2(pk2(wv.z,wv.z),a0,acc[2][0]); acc[2][1]=fma2(pk2(wv.z,wv.z),a1,acc[2][1]);
            acc[3][0]=fma2(pk2(wv.w,wv.w),a0,acc[3][0]); acc[3][1]=fma2(pk2(wv.w,wv.w),a1,acc[3][1]);
        }
        if (kse == 1) {
            #pragma unroll
            for (int q = 0; q < 4; q++) {
                *(u64*)&sm[O2T + (ob+q)*34 + row0]     = acc[q][0];
                *(u64*)&sm[O2T + (ob+q)*34 + row0 + 2] = acc[q][1];
            }
        }
        __syncthreads();
        if (kse == 0) {
            #pragma unroll
            for (int q = 0; q < 4; q++) {
                u64 p0 = *(const u64*)&sm[O2T + (ob+q)*34 + row0];
                u64 p1 = *(const u64*)&sm[O2T + (ob+q)*34 + row0 + 2];
                *(u64*)&sm[O2T + (ob+q)*34 + row0]     = add2(acc[q][0], p0);
                *(u64*)&sm[O2T + (ob+q)*34 + row0 + 2] = add2(acc[q][1], p1);
            }
        }
    }
    cp_waitall();          // SE weights landed
    __syncthreads();

    // ============ stage F: T1 = relu(Se1 . o2) -> T1T[i][34]  (4 warps) ============
    if (w < 4) {
        const int fr = w*8 + rg*2;             // row pair
        u64 a0 = 0ull, a1 = 0ull, a2 = 0ull, a3 = 0ull;
        #pragma unroll 4
        for (int oc = 0; oc < 128; oc++) {
            float4 wv = *(const float4*)&sm[W1 + oc*32 + jl*4];
            u64 op = *(const u64*)&sm[O2T + oc*34 + fr];
            a0 = fma2(pk2(wv.x,wv.x), op, a0);
            a1 = fma2(pk2(wv.y,wv.y), op, a1);
            a2 = fma2(pk2(wv.z,wv.z), op, a2);
            a3 = fma2(pk2(wv.w,wv.w), op, a3);
        }
        float lo, hi;
        upk(a0, lo, hi); *(u64*)&sm[SS + (jl*4+0)*34 + fr] = pk2(fmaxf(lo,0.f), fmaxf(hi,0.f));
        upk(a1, lo, hi); *(u64*)&sm[SS + (jl*4+1)*34 + fr] = pk2(fmaxf(lo,0.f), fmaxf(hi,0.f));
        upk(a2, lo, hi); *(u64*)&sm[SS + (jl*4+2)*34 + fr] = pk2(fmaxf(lo,0.f), fmaxf(hi,0.f));
        upk(a3, lo, hi); *(u64*)&sm[SS + (jl*4+3)*34 + fr] = pk2(fmaxf(lo,0.f), fmaxf(hi,0.f));
    }
    __syncthreads();

    // ============ stage G: o2 *= sigmoid(Se2 . T1) ============
    {
        const int qg = w & 3, rq = w >> 2;
        const int ob = qg*32 + jl*4;
        const int rpos = rq*8 + rg*2;
        u64 a0 = 0ull, a1 = 0ull, a2 = 0ull, a3 = 0ull;
        #pragma unroll 4
        for (int i = 0; i < 32; i++) {
            float4 wv = *(const float4*)&sm[W1 + 4096 + i*128 + ob];
            u64 tp = *(const u64*)&sm[SS + i*34 + rpos];
            a0 = fma2(pk2(wv.x,wv.x), tp, a0);
            a1 = fma2(pk2(wv.y,wv.y), tp, a1);
            a2 = fma2(pk2(wv.z,wv.z), tp, a2);
            a3 = fma2(pk2(wv.w,wv.w), tp, a3);
        }
        u64 se[4] = {a0, a1, a2, a3};
        #pragma unroll
        for (int q = 0; q < 4; q++) {
            float lo, hi; upk(se[q], lo, hi);
            const int a = O2T + (ob+q)*34 + rpos;
            sm[a]   *= sigm(lo);
            sm[a+1] *= sigm(hi);
        }
    }
    __syncthreads();

    // ============ stage H: residual gate ============
    {
        const float bgv = __ldg(bg);
        #pragma unroll
        for (int r2 = 0; r2 < 2; r2++) {
            const int row = 2*w + r2;
            float p = 0.0f;
            #pragma unroll
            for (int k = 0; k < 4; k++) {
                const int cx = lane + 32*k;
                p += sm[W1 + 8192 + cx]       * sm[XT  + cx*34 + row];
                p += sm[W1 + 8192 + 128 + cx] * sm[O2T + cx*34 + row];
            }
            #pragma unroll
            for (int o = 16; o; o >>= 1) p += __shfl_xor_sync(0xffffffffu, p, o);
            if (lane == 0) sm[GG + row] = sigm(p + bgv);
        }
    }
    __syncthreads();

    // ============ stage I: out = g*o3 + (1-g)*x ============
    {
        float4* og4 = (float4*)out + rowBase*32;
        #pragma unroll
        for (int it = 0; it < 2; it++) {
            const int idx = t + 512*it;
            const int r = idx >> 5, c4 = idx & 31;
            const float g = sm[GG + r];
            float4 res;
            res.x = g*sm[O2T + (c4*4+0)*34 + r] + (1.0f-g)*sm[XT + (c4*4+0)*34 + r];
            res.y = g*sm[O2T + (c4*4+1)*34 + r] + (1.0f-g)*sm[XT + (c4*4+1)*34 + r];
            res.z = g*sm[O2T + (c4*4+2)*34 + r] + (1.0f-g)*sm[XT + (c4*4+2)*34 + r];
            res.w = g*sm[O2T + (c4*4+3)*34 + r] + (1.0f-g)*sm[XT + (c4*4+3)*34 + r];
            og4[idx] = res;
        }
    }
}

// =======================================================================
extern "C" void kernel_launch(void* const* d_in, const int* in_sizes, int n_in,
                              void* d_out, int out_size)
{
    const float* x    = (const float*)d_in[0];
    const float* nb   = (const float*)d_in[1];
    const float* Wq   = (const float*)d_in[2];
    const float* bq   = (const float*)d_in[3];
    const float* Wk   = (const float*)d_in[4];
    // d_in[5] = bk : constant over n => softmax-invariant, unused
    const float* Wv   = (const float*)d_in[6];
    const float* bv   = (const float*)d_in[7];
    const float* Wo   = (const float*)d_in[8];
    const float* bo   = (const float*)d_in[9];
    const float* Wse1 = (const float*)d_in[10];
    const float* Wse2 = (const float*)d_in[11];
    const float* Wg   = (const float*)d_in[12];
    const float* bg   = (const float*)d_in[13];
    float* out = (float*)d_out;

    cudaFuncSetAttribute(k_fused, cudaFuncAttributeMaxDynamicSharedMemorySize,
                         SMEM_FLOATS * 4);

    k_pre<<<64, 256>>>(Wq, bq, Wv, Wo, Wse1, Wse2);
    k_fused<<<2048, 512, SMEM_FLOATS * 4>>>(x, nb, Wk, bv, bo, Wg, bg, out);
}

// round 10
// speedup vs baseline: 1.1436x; 1.0115x over previous
#include <cuda_runtime.h>
#include <math.h>

typedef unsigned long long u64;

// ---------------- pretransposed weights (device scratch) ----------------
__device__ float g_WqT[16384];   // [c][j] = Wq[j][c] * 1/sqrt(32)
__device__ float g_WvT[16384];   // [c][j] = Wv[j][c]
__device__ float g_WoP[16384];   // [j][oc] = Wo[oc][(j&31)*4 + (j>>5)]  (permute folded)
__device__ float g_Se1T[4096];   // [oc][i] = Wse1[i][oc]
__device__ float g_Se2T[4096];   // [i][oc] = Wse2[oc][i]
__device__ float g_bqs[128];     // bq * 1/sqrt(32)

#define SCALE 0.17677669529663687f

__global__ void k_pre(const float* __restrict__ Wq, const float* __restrict__ bq,
                      const float* __restrict__ Wv, const float* __restrict__ Wo,
                      const float* __restrict__ Wse1, const float* __restrict__ Wse2)
{
    int i = blockIdx.x * 256 + threadIdx.x;
    if (i < 16384) {
        int a = i >> 7, b = i & 127;
        g_WqT[i] = Wq[b*128 + a] * SCALE;      // WqT[c][j]
        g_WvT[i] = Wv[b*128 + a];              // WvT[c][j]
        int j = a, oc = b;
        g_WoP[i] = Wo[oc*128 + ((j & 31)*4 + (j >> 5))];
    }
    if (i < 4096) {
        int oc1 = i >> 5, i1 = i & 31;
        g_Se1T[i] = Wse1[i1*128 + oc1];
        int i2 = i >> 7, oc2 = i & 127;
        g_Se2T[i] = Wse2[oc2*32 + i2];
    }
    if (i < 128) g_bqs[i] = bq[i] * SCALE;
}

// ---------------- helpers ----------------
__device__ __forceinline__ u64 pk2(float lo, float hi) {
    u64 r; asm("mov.b64 %0, {%1, %2};" : "=l"(r) : "f"(lo), "f"(hi)); return r;
}
__device__ __forceinline__ void upk(u64 v, float& lo, float& hi) {
    asm("mov.b64 {%0, %1}, %2;" : "=f"(lo), "=f"(hi) : "l"(v));
}
__device__ __forceinline__ u64 fma2(u64 a, u64 b, u64 c) {
    u64 d; asm("fma.rn.f32x2 %0, %1, %2, %3;" : "=l"(d) : "l"(a), "l"(b), "l"(c)); return d;
}
__device__ __forceinline__ u64 add2(u64 a, u64 b) {
    u64 d; asm("add.rn.f32x2 %0, %1, %2;" : "=l"(d) : "l"(a), "l"(b)); return d;
}
__device__ __forceinline__ void cpa16(unsigned dst, const void* src) {
    asm volatile("cp.async.cg.shared.global [%0], [%1], 16;" :: "r"(dst), "l"(src));
}
__device__ __forceinline__ void cp_commit() { asm volatile("cp.async.commit_group;"); }
__device__ __forceinline__ void cp_waitall() { asm volatile("cp.async.wait_group 0;" ::: "memory"); }
__device__ __forceinline__ float sigm(float z) { return 1.0f / (1.0f + __expf(-z)); }

// ---------------- smem layout (floats), 32 rows/block ----------------
#define W1   0        // 16384: WqT -> WvT -> [Se1T | Se2T@+4096 | Wg@+8192]
#define W2   16384    // 16384: Wk (natural [j][c]) -> WoP
#define CTX  32768    // 17408: qT[128][34]@0 + A-partials@+4352(3x4352)
                      //        -> qk[32][512] -> ctxT[(h*128+c)][34]
#define APART (CTX + 4352)
#define OT   (CTX + 13056)   // oT[j][34] (over ctxT tail, h=3)
#define O2T  (CTX + 0)       // o2T[oc][34] (over ctxT head)
#define XT   50176    // 4352: xT[128][34]
#define SS   54528    // 2560: attn[row][n][4h] -> T1T[i][34]
#define GG   57088    // 32 gates
#define SMEM_FLOATS 57120    // 228480 B

__global__ void __launch_bounds__(512, 1) k_fused(
    const float* __restrict__ x,
    const float* __restrict__ nb,
    const float* __restrict__ Wk,
    const float* __restrict__ bv, const float* __restrict__ bo,
    const float* __restrict__ Wg, const float* __restrict__ bg,
    float* __restrict__ out)
{
    extern __shared__ float sm[];
    const int t = threadIdx.x;
    const int lane = t & 31;
    const int w = t >> 5;               // warp 0..15
    const int jl = lane & 7;            // j-lane (8)
    const int rg = lane >> 3;           // row-group (4)
    const long rowBase = (long)blockIdx.x * 32;
    unsigned sb = (unsigned)__cvta_generic_to_shared(sm);

    // ============ phase 0: WqT->W1, Wk->W2 (cp.async); build xT ============
    #pragma unroll
    for (int i = t; i < 4096; i += 512) cpa16(sb + W1*4 + i*16, g_WqT + i*4);
    #pragma unroll
    for (int i = t; i < 4096; i += 512) cpa16(sb + W2*4 + i*16, Wk + i*4);
    cp_commit();
    {
        const float4* xg = (const float4*)x + rowBase*32;
        #pragma unroll
        for (int it = 0; it < 2; it++) {
            int idx = t + 512*it;
            int r = idx >> 5, c4 = idx & 31;
            float4 v = xg[idx];
            sm[XT + (c4*4+0)*34 + r] = v.x;
            sm[XT + (c4*4+1)*34 + r] = v.y;
            sm[XT + (c4*4+2)*34 + r] = v.z;
            sm[XT + (c4*4+3)*34 + r] = v.w;
        }
    }
    cp_waitall();
    __syncthreads();

    // ============ stage A: q = s*(Wq x + bq), split-k x4 -> qT[j][34] ============
    {
        const int qg = w & 3, ks = w >> 2;
        const int jb = qg*32 + jl*4;
        u64 acc[4][4];                       // [q][pair]
        #pragma unroll
        for (int q = 0; q < 4; q++) {
            u64 init = 0ull;
            if (ks == 0) { float b = g_bqs[jb+q]; init = pk2(b, b); }
            #pragma unroll
            for (int p = 0; p < 4; p++) acc[q][p] = init;
        }
        #pragma unroll 4
        for (int c = ks*32; c < ks*32 + 32; c++) {
            float4 wv = *(const float4*)&sm[W1 + c*128 + jb];
            u64 x0 = *(const u64*)&sm[XT + c*34 + rg*8 + 0];
            u64 x1 = *(const u64*)&sm[XT + c*34 + rg*8 + 2];
            u64 x2 = *(const u64*)&sm[XT + c*34 + rg*8 + 4];
            u64 x3 = *(const u64*)&sm[XT + c*34 + rg*8 + 6];
            u64 w0 = pk2(wv.x,wv.x), w1 = pk2(wv.y,wv.y);
            u64 w2 = pk2(wv.z,wv.z), w3 = pk2(wv.w,wv.w);
            acc[0][0]=fma2(w0,x0,acc[0][0]); acc[0][1]=fma2(w0,x1,acc[0][1]);
            acc[0][2]=fma2(w0,x2,acc[0][2]); acc[0][3]=fma2(w0,x3,acc[0][3]);
            acc[1][0]=fma2(w1,x0,acc[1][0]); acc[1][1]=fma2(w1,x1,acc[1][1]);
            acc[1][2]=fma2(w1,x2,acc[1][2]); acc[1][3]=fma2(w1,x3,acc[1][3]);
            acc[2][0]=fma2(w2,x0,acc[2][0]); acc[2][1]=fma2(w2,x1,acc[2][1]);
            acc[2][2]=fma2(w2,x2,acc[2][2]); acc[2][3]=fma2(w2,x3,acc[2][3]);
            acc[3][0]=fma2(w3,x0,acc[3][0]); acc[3][1]=fma2(w3,x1,acc[3][1]);
            acc[3][2]=fma2(w3,x2,acc[3][2]); acc[3][3]=fma2(w3,x3,acc[3][3]);
        }
        if (ks) {
            float* P = sm + APART + (ks-1)*4352;
            #pragma unroll
            for (int q = 0; q < 4; q++)
                #pragma unroll
                for (int p = 0; p < 4; p++)
                    *(u64*)&P[(jb+q)*34 + rg*8 + 2*p] = acc[q][p];
        }
        __syncthreads();
        // W1 (WqT) dead -> prefetch WvT
        #pragma unroll
        for (int i = t; i < 4096; i += 512) cpa16(sb + W1*4 + i*16, g_WvT + i*4);
        cp_commit();
        if (ks == 0) {
            #pragma unroll
            for (int pt = 0; pt < 3; pt++) {
                const float* P = sm + APART + pt*4352;
                #pragma unroll
                for (int q = 0; q < 4; q++)
                    #pragma unroll
                    for (int p = 0; p < 4; p++)
                        acc[q][p] = add2(acc[q][p], *(const u64*)&P[(jb+q)*34 + rg*8 + 2*p]);
            }
            #pragma unroll
            for (int q = 0; q < 4; q++)
                #pragma unroll
                for (int p = 0; p < 4; p++)
                    *(u64*)&sm[CTX + (jb+q)*34 + rg*8 + 2*p] = acc[q][p];
        }
    }
    __syncthreads();

    // ============ stage B: qk[row][h*128+c] = sum_d q[row][h*32+d]*Wk[h*32+d][c] ============
    {
        const int h = w & 3, cs = w >> 2;
        const int cb = cs*32 + jl*4;                  // c-quad within head
        u64 acc[4][4];
        #pragma unroll
        for (int q = 0; q < 4; q++)
            #pragma unroll
            for (int p = 0; p < 4; p++) acc[q][p] = 0ull;
        #pragma unroll 4
        for (int d = 0; d < 32; d++) {
            const int j = h*32 + d;
            float4 wv = *(const float4*)&sm[W2 + j*128 + cb];
            u64 q0 = *(const u64*)&sm[CTX + j*34 + rg*8 + 0];
            u64 q1 = *(const u64*)&sm[CTX + j*34 + rg*8 + 2];
            u64 q2 = *(const u64*)&sm[CTX + j*34 + rg*8 + 4];
            u64 q3 = *(const u64*)&sm[CTX + j*34 + rg*8 + 6];
            u64 w0 = pk2(wv.x,wv.x), w1 = pk2(wv.y,wv.y);
            u64 w2_ = pk2(wv.z,wv.z), w3 = pk2(wv.w,wv.w);
            acc[0][0]=fma2(w0,q0,acc[0][0]); acc[0][1]=fma2(w0,q1,acc[0][1]);
            acc[0][2]=fma2(w0,q2,acc[0][2]); acc[0][3]=fma2(w0,q3,acc[0][3]);
            acc[1][0]=fma2(w1,q0,acc[1][0]); acc[1][1]=fma2(w1,q1,acc[1][1]);
            acc[1][2]=fma2(w1,q2,acc[1][2]); acc[1][3]=fma2(w1,q3,acc[1][3]);
            acc[2][0]=fma2(w2_,q0,acc[2][0]); acc[2][1]=fma2(w2_,q1,acc[2][1]);
            acc[2][2]=fma2(w2_,q2,acc[2][2]); acc[2][3]=fma2(w2_,q3,acc[2][3]);
            acc[3][0]=fma2(w3,q0,acc[3][0]); acc[3][1]=fma2(w3,q1,acc[3][1]);
            acc[3][2]=fma2(w3,q2,acc[3][2]); acc[3][3]=fma2(w3,q3,acc[3][3]);
        }
        __syncthreads();        // qT reads drained before qk overwrites region
        #pragma unroll
        for (int p = 0; p < 4; p++) {
            float l0,h0,l1,h1,l2,h2,l3,h3;
            upk(acc[0][p], l0, h0); upk(acc[1][p], l1, h1);
            upk(acc[2][p], l2, h2); upk(acc[3][p], l3, h3);
            *(float4*)&sm[CTX + (rg*8+2*p  )*512 + h*128 + cb] = make_float4(l0,l1,l2,l3);
            *(float4*)&sm[CTX + (rg*8+2*p+1)*512 + h*128 + cb] = make_float4(h0,h1,h2,h3);
        }
    }
    __syncthreads();
    // W2 (Wk) dead -> prefetch WoP
    #pragma unroll
    for (int i = t; i < 4096; i += 512) cpa16(sb + W2*4 + i*16, g_WoP + i*4);
    cp_commit();

    // ============ stage C1+C2: scores + softmax, warp-per-row ============
    // warp = row (2 passes), lane = n (lanes 20..31 padded).
    // qk reads are full-warp broadcasts (1 wf each); dot via f32x2 c-pairs.
    #pragma unroll
    for (int pass = 0; pass < 2; pass++) {
        const int row = w + pass*16;
        const int n = (lane < 20) ? lane : 19;
        const float* nbr = nb + (((rowBase + row)*20 + n) << 7);
        const float* qkr = sm + CTX + row*512;
        u64 acc[4][2];
        #pragma unroll
        for (int h = 0; h < 4; h++) { acc[h][0] = 0ull; acc[h][1] = 0ull; }
        #pragma unroll 4
        for (int c4 = 0; c4 < 32; c4++) {
            float4 v = *(const float4*)(nbr + c4*4);          // LDG.128
            u64 v01 = pk2(v.x, v.y), v23 = pk2(v.z, v.w);
            #pragma unroll
            for (int h = 0; h < 4; h++) {
                float4 qv = *(const float4*)(qkr + h*128 + c4*4);  // LDS.128 broadcast
                acc[h][0] = fma2(pk2(qv.x, qv.y), v01, acc[h][0]);
                acc[h][1] = fma2(pk2(qv.z, qv.w), v23, acc[h][1]);
            }
        }
        float sc[4];
        #pragma unroll
        for (int h = 0; h < 4; h++) {
            u64 s2 = add2(acc[h][0], acc[h][1]);
            float lo, hi; upk(s2, lo, hi);
            sc[h] = (lane < 20) ? (lo + hi) : -1e30f;
        }
        // softmax across lanes (pad lanes contribute exp(-inf)=0)
        float m[4];
        #pragma unroll
        for (int h = 0; h < 4; h++) m[h] = sc[h];
        #pragma unroll
        for (int o = 16; o; o >>= 1) {
            #pragma unroll
            for (int h = 0; h < 4; h++)
                m[h] = fmaxf(m[h], __shfl_xor_sync(0xffffffffu, m[h], o));
        }
        float e[4], s[4];
        #pragma unroll
        for (int h = 0; h < 4; h++) { e[h] = __expf(sc[h] - m[h]); s[h] = e[h]; }
        #pragma unroll
        for (int o = 16; o; o >>= 1) {
            #pragma unroll
            for (int h = 0; h < 4; h++)
                s[h] += __shfl_xor_sync(0xffffffffu, s[h], o);
        }
        if (lane < 20)
            *(float4*)&sm[SS + row*80 + lane*4] =
                make_float4(e[0]/s[0], e[1]/s[1], e[2]/s[2], e[3]/s[3]);
    }
    __syncthreads();

    // ============ stage C3: ctxT[(h*128+c)][34] ============
    {
        const int cq = w & 3, rq3 = w >> 2;
        const int c = cq*32 + lane;
        u64 cacc[8][2];
        #pragma unroll
        for (int r = 0; r < 8; r++) { cacc[r][0] = 0ull; cacc[r][1] = 0ull; }
        #pragma unroll
        for (int r = 0; r < 8; r++) {
            const int row = rq3*8 + r;
            const float* nbr = nb + ((rowBase + row)*20 << 7) + c;
            #pragma unroll 4
            for (int n = 0; n < 20; n++) {
                float v = __ldg(nbr + n*128);
                u64 vp = pk2(v, v);
                float4 at = *(const float4*)&sm[SS + row*80 + n*4];
                cacc[r][0] = fma2(pk2(at.x, at.y), vp, cacc[r][0]);
                cacc[r][1] = fma2(pk2(at.z, at.w), vp, cacc[r][1]);
            }
        }
        __syncthreads();   // qk fully consumed before ctxT overwrites region
        #pragma unroll
        for (int r = 0; r < 8; r++) {
            const int row = rq3*8 + r;
            float v0, v1, v2, v3;
            upk(cacc[r][0], v0, v1);
            upk(cacc[r][1], v2, v3);
            sm[CTX + (0*128 + c)*34 + row] = v0;
            sm[CTX + (1*128 + c)*34 + row] = v1;
            sm[CTX + (2*128 + c)*34 + row] = v2;
            sm[CTX + (3*128 + c)*34 + row] = v3;
        }
    }
    cp_waitall();          // WvT / WoP landed
    __syncthreads();

    // ============ stage D: o = Wv ctx + bv -> oT[h*32+d][34], split-k x2 ============
    {
        const int h = w & 3, ksd = (w >> 2) & 1, rs = w >> 3;
        const int jb = h*32 + jl*4;
        const int row0 = rs*16 + rg*4;       // pairs at row0, row0+2
        u64 acc[4][2];
        #pragma unroll
        for (int q = 0; q < 4; q++) {
            u64 init = 0ull;
            if (ksd == 0) { float b = __ldg(&bv[jb+q]); init = pk2(b, b); }
            acc[q][0] = init; acc[q][1] = init;
        }
        #pragma unroll 4
        for (int c = ksd*64; c < ksd*64 + 64; c++) {
            float4 wv = *(const float4*)&sm[W1 + c*128 + jb];
            u64 a0 = *(const u64*)&sm[CTX + (h*128 + c)*34 + row0];
            u64 a1 = *(const u64*)&sm[CTX + (h*128 + c)*34 + row0 + 2];
            acc[0][0]=fma2(pk2(wv.x,wv.x),a0,acc[0][0]); acc[0][1]=fma2(pk2(wv.x,wv.x),a1,acc[0][1]);
            acc[1][0]=fma2(pk2(wv.y,wv.y),a0,acc[1][0]); acc[1][1]=fma2(pk2(wv.y,wv.y),a1,acc[1][1]);
            acc[2][0]=fma2(pk2(wv.z,wv.z),a0,acc[2][0]); acc[2][1]=fma2(pk2(wv.z,wv.z),a1,acc[2][1]);
            acc[3][0]=fma2(pk2(wv.w,wv.w),a0,acc[3][0]); acc[3][1]=fma2(pk2(wv.w,wv.w),a1,acc[3][1]);
        }
        __syncthreads();       // all ctxT reads done before oT (h=3 region) overwritten
        if (ksd == 1) {
            #pragma unroll
            for (int q = 0; q < 4; q++) {
                *(u64*)&sm[OT + (jb+q)*34 + row0]     = acc[q][0];
                *(u64*)&sm[OT + (jb+q)*34 + row0 + 2] = acc[q][1];
            }
        }
        __syncthreads();
        // W1 (WvT) dead -> prefetch SE weights
        #pragma unroll
        for (int i = t; i < 1024; i += 512) cpa16(sb + W1*4 + i*16, g_Se1T + i*4);
        #pragma unroll
        for (int i = t; i < 1024; i += 512) cpa16(sb + (W1+4096)*4 + i*16, g_Se2T + i*4);
        if (t < 64) cpa16(sb + (W1+8192)*4 + t*16, Wg + t*4);
        cp_commit();
        if (ksd == 0) {
            #pragma unroll
            for (int q = 0; q < 4; q++) {
                u64 p0 = *(const u64*)&sm[OT + (jb+q)*34 + row0];
                u64 p1 = *(const u64*)&sm[OT + (jb+q)*34 + row0 + 2];
                *(u64*)&sm[OT + (jb+q)*34 + row0]     = add2(acc[q][0], p0);
                *(u64*)&sm[OT + (jb+q)*34 + row0 + 2] = add2(acc[q][1], p1);
            }
        }
    }
    __syncthreads();

    // ============ stage E: o2 = WoP . o + bo -> o2T[oc][34], split-k x2 ============
    {
        const int qg = w & 3, kse = (w >> 2) & 1, rs = w >> 3;
        const int ob = qg*32 + jl*4;
        const int row0 = rs*16 + rg*4;
        u64 acc[4][2];
        #pragma unroll
        for (int q = 0; q < 4; q++) {
            u64 init = 0ull;
            if (kse == 0) { float b = __ldg(&bo[ob+q]); init = pk2(b, b); }
            acc[q][0] = init; acc[q][1] = init;
        }
        #pragma unroll 4
        for (int j = kse*64; j < kse*64 + 64; j++) {
            float4 wv = *(const float4*)&sm[W2 + j*128 + ob];
            u64 a0 = *(const u64*)&sm[OT + j*34 + row0];
            u64 a1 = *(const u64*)&sm[OT + j*34 + row0 + 2];
            acc[0][0]=fma2(pk2(wv.x,wv.x),a0,acc[0][0]); acc[0][1]=fma2(pk2(wv.x,wv.x),a1,acc[0][1]);
            acc[1][0]=fma2(pk2(wv.y,wv.y),a0,acc[1][0]); acc[1][1]=fma2(pk2(wv.y,wv.y),a1,acc[1][1]);
            acc[2][0]=fma2(pk2(wv.z,wv.z),a0,acc[2][0]); acc[2][1]=fma2(pk2(wv.z,wv.z),a1,acc[2][1]);
            acc[3][0]=fma2(pk2(wv.w,wv.w),a0,acc[3][0]); acc[3][1]=fma2(pk2(wv.w,wv.w),a1,acc[3][1]);
        }
        if (kse == 1) {
            #pragma unroll
            for (int q = 0; q < 4; q++) {
                *(u64*)&sm[O2T + (ob+q)*34 + row0]     = acc[q][0];
                *(u64*)&sm[O2T + (ob+q)*34 + row0 + 2] = acc[q][1];
            }
        }
        __syncthreads();
        if (kse == 0) {
            #pragma unroll
            for (int q = 0; q < 4; q++) {
                u64 p0 = *(const u64*)&sm[O2T + (ob+q)*34 + row0];
                u64 p1 = *(const u64*)&sm[O2T + (ob+q)*34 + row0 + 2];
                *(u64*)&sm[O2T + (ob+q)*34 + row0]     = add2(acc[q][0], p0);
                *(u64*)&sm[O2T + (ob+q)*34 + row0 + 2] = add2(acc[q][1], p1);
            }
        }
    }
    cp_waitall();          // SE weights landed
    __syncthreads();

    // ============ stage F: T1 = relu(Se1 . o2) -> T1T[i][34]  (4 warps) ============
    if (w < 4) {
        const int fr = w*8 + rg*2;             // row pair
        u64 a0 = 0ull, a1 = 0ull, a2 = 0ull, a3 = 0ull;
        #pragma unroll 4
        for (int oc = 0; oc < 128; oc++) {
            float4 wv = *(const float4*)&sm[W1 + oc*32 + jl*4];
            u64 op = *(const u64*)&sm[O2T + oc*34 + fr];
            a0 = fma2(pk2(wv.x,wv.x), op, a0);
            a1 = fma2(pk2(wv.y,wv.y), op, a1);
            a2 = fma2(pk2(wv.z,wv.z), op, a2);
            a3 = fma2(pk2(wv.w,wv.w), op, a3);
        }
        float lo, hi;
        upk(a0, lo, hi); *(u64*)&sm[SS + (jl*4+0)*34 + fr] = pk2(fmaxf(lo,0.f), fmaxf(hi,0.f));
        upk(a1, lo, hi); *(u64*)&sm[SS + (jl*4+1)*34 + fr] = pk2(fmaxf(lo,0.f), fmaxf(hi,0.f));
        upk(a2, lo, hi); *(u64*)&sm[SS + (jl*4+2)*34 + fr] = pk2(fmaxf(lo,0.f), fmaxf(hi,0.f));
        upk(a3, lo, hi); *(u64*)&sm[SS + (jl*4+3)*34 + fr] = pk2(fmaxf(lo,0.f), fmaxf(hi,0.f));
    }
    __syncthreads();

    // ============ stage G: o2 *= sigmoid(Se2 . T1) ============
    {
        const int qg = w & 3, rq = w >> 2;
        const int ob = qg*32 + jl*4;
        const int rpos = rq*8 + rg*2;
        u64 a0 = 0ull, a1 = 0ull, a2 = 0ull, a3 = 0ull;
        #pragma unroll 4
        for (int i = 0; i < 32; i++) {
            float4 wv = *(const float4*)&sm[W1 + 4096 + i*128 + ob];
            u64 tp = *(const u64*)&sm[SS + i*34 + rpos];
            a0 = fma2(pk2(wv.x,wv.x), tp, a0);
            a1 = fma2(pk2(wv.y,wv.y), tp, a1);
            a2 = fma2(pk2(wv.z,wv.z), tp, a2);
            a3 = fma2(pk2(wv.w,wv.w), tp, a3);
        }
        u64 se[4] = {a0, a1, a2, a3};
        #pragma unroll
        for (int q = 0; q < 4; q++) {
            float lo, hi; upk(se[q], lo, hi);
            const int a = O2T + (ob+q)*34 + rpos;
            sm[a]   *= sigm(lo);
            sm[a+1] *= sigm(hi);
        }
    }
    __syncthreads();

    // ============ stage H: residual gate ============
    {
        const float bgv = __ldg(bg);
        #pragma unroll
        for (int r2 = 0; r2 < 2; r2++) {
            const int row = 2*w + r2;
            float p = 0.0f;
            #pragma unroll
            for (int k = 0; k < 4; k++) {
                const int cx = lane + 32*k;
                p += sm[W1 + 8192 + cx]       * sm[XT  + cx*34 + row];
                p += sm[W1 + 8192 + 128 + cx] * sm[O2T + cx*34 + row];
            }
            #pragma unroll
            for (int o = 16; o; o >>= 1) p += __shfl_xor_sync(0xffffffffu, p, o);
            if (lane == 0) sm[GG + row] = sigm(p + bgv);
        }
    }
    __syncthreads();

    // ============ stage I: out = g*o3 + (1-g)*x ============
    {
        float4* og4 = (float4*)out + rowBase*32;
        #pragma unroll
        for (int it = 0; it < 2; it++) {
            const int idx = t + 512*it;
            const int r = idx >> 5, c4 = idx & 31;
            const float g = sm[GG + r];
            float4 res;
            res.x = g*sm[O2T + (c4*4+0)*34 + r] + (1.0f-g)*sm[XT + (c4*4+0)*34 + r];
            res.y = g*sm[O2T + (c4*4+1)*34 + r] + (1.0f-g)*sm[XT + (c4*4+1)*34 + r];
            res.z = g*sm[O2T + (c4*4+2)*34 + r] + (1.0f-g)*sm[XT + (c4*4+2)*34 + r];
            res.w = g*sm[O2T + (c4*4+3)*34 + r] + (1.0f-g)*sm[XT + (c4*4+3)*34 + r];
            og4[idx] = res;
        }
    }
}

// =======================================================================
extern "C" void kernel_launch(void* const* d_in, const int* in_sizes, int n_in,
                              void* d_out, int out_size)
{
    const float* x    = (const float*)d_in[0];
    const float* nb   = (const float*)d_in[1];
    const float* Wq   = (const float*)d_in[2];
    const float* bq   = (const float*)d_in[3];
    const float* Wk   = (const float*)d_in[4];
    // d_in[5] = bk : constant over n => softmax-invariant, unused
    const float* Wv   = (const float*)d_in[6];
    const float* bv   = (const float*)d_in[7];
    const float* Wo   = (const float*)d_in[8];
    const float* bo   = (const float*)d_in[9];
    const float* Wse1 = (const float*)d_in[10];
    const float* Wse2 = (const float*)d_in[11];
    const float* Wg   = (const float*)d_in[12];
    const float* bg   = (const float*)d_in[13];
    float* out = (float*)d_out;

    cudaFuncSetAttribute(k_fused, cudaFuncAttributeMaxDynamicSharedMemorySize,
                         SMEM_FLOATS * 4);

    k_pre<<<64, 256>>>(Wq, bq, Wv, Wo, Wse1, Wse2);
    k_fused<<<2048, 512, SMEM_FLOATS * 4>>>(x, nb, Wk, bv, bo, Wg, bg, out);
}

// round 11
// speedup vs baseline: 1.3703x; 1.1983x over previous
#include <cuda_runtime.h>
#include <math.h>

typedef unsigned long long u64;

// ---------------- pretransposed tf32 weights (device scratch) ----------------
__device__ float g_WqT[16384];   // [c][j]  = tf32(Wq[j][c] * 1/sqrt(32))
__device__ float g_WkN[16384];   // [j][c]  = tf32(Wk[j][c])
__device__ float g_WvT[16384];   // [c][j]  = tf32(Wv[j][c])
__device__ float g_WoP[16384];   // [j][oc] = tf32(Wo[oc][(j&31)*4 + (j>>5)])
__device__ float g_Se1T[4096];   // [oc][i] = tf32(Wse1[i][oc])
__device__ float g_Se2T[4096];   // [i][oc] = tf32(Wse2[oc][i])
__device__ float g_bqs[128];     // bq * 1/sqrt(32)  (fp32 exact)

#define SCALE 0.17677669529663687f

__device__ __forceinline__ unsigned f2tf(float f) {
    unsigned r; asm("cvt.rna.tf32.f32 %0, %1;" : "=r"(r) : "f"(f)); return r;
}

__global__ void k_pre(const float* __restrict__ Wq, const float* __restrict__ bq,
                      const float* __restrict__ Wk,
                      const float* __restrict__ Wv, const float* __restrict__ Wo,
                      const float* __restrict__ Wse1, const float* __restrict__ Wse2)
{
    int i = blockIdx.x * 256 + threadIdx.x;
    if (i < 16384) {
        int a = i >> 7, b = i & 127;
        g_WqT[i] = __uint_as_float(f2tf(Wq[b*128 + a] * SCALE));
        g_WkN[i] = __uint_as_float(f2tf(Wk[i]));
        g_WvT[i] = __uint_as_float(f2tf(Wv[b*128 + a]));
        int j = a, oc = b;
        g_WoP[i] = __uint_as_float(f2tf(Wo[oc*128 + ((j & 31)*4 + (j >> 5))]));
    }
    if (i < 4096) {
        int oc1 = i >> 5, i1 = i & 31;
        g_Se1T[i] = __uint_as_float(f2tf(Wse1[i1*128 + oc1]));
        int i2 = i >> 7, oc2 = i & 127;
        g_Se2T[i] = __uint_as_float(f2tf(Wse2[oc2*32 + i2]));
    }
    if (i < 128) g_bqs[i] = bq[i] * SCALE;
}

// ---------------- helpers ----------------
__device__ __forceinline__ u64 pk2(float lo, float hi) {
    u64 r; asm("mov.b64 %0, {%1, %2};" : "=l"(r) : "f"(lo), "f"(hi)); return r;
}
__device__ __forceinline__ void upk(u64 v, float& lo, float& hi) {
    asm("mov.b64 {%0, %1}, %2;" : "=f"(lo), "=f"(hi) : "l"(v));
}
__device__ __forceinline__ u64 fma2(u64 a, u64 b, u64 c) {
    u64 d; asm("fma.rn.f32x2 %0, %1, %2, %3;" : "=l"(d) : "l"(a), "l"(b), "l"(c)); return d;
}
__device__ __forceinline__ u64 add2(u64 a, u64 b) {
    u64 d; asm("add.rn.f32x2 %0, %1, %2;" : "=l"(d) : "l"(a), "l"(b)); return d;
}
__device__ __forceinline__ void mma8(float d[4], const unsigned a[4],
                                     unsigned b0, unsigned b1) {
    asm volatile(
        "mma.sync.aligned.m16n8k8.row.col.f32.tf32.tf32.f32 "
        "{%0,%1,%2,%3}, {%4,%5,%6,%7}, {%8,%9}, {%0,%1,%2,%3};"
        : "+f"(d[0]), "+f"(d[1]), "+f"(d[2]), "+f"(d[3])
        : "r"(a[0]), "r"(a[1]), "r"(a[2]), "r"(a[3]), "r"(b0), "r"(b1));
}
__device__ __forceinline__ void cpa16(unsigned dst, const void* src) {
    asm volatile("cp.async.cg.shared.global [%0], [%1], 16;" :: "r"(dst), "l"(src));
}
__device__ __forceinline__ void cp_commit() { asm volatile("cp.async.commit_group;"); }
__device__ __forceinline__ void cp_waitall() { asm volatile("cp.async.wait_group 0;" ::: "memory"); }
__device__ __forceinline__ float sigm(float z) { return 1.0f / (1.0f + __expf(-z)); }

// ---------------- smem layout (floats), 32 rows/block ----------------
#define W1   0        // 16896: WqT[c][j](132) -> WvT -> [Se1T(36)|Se2T(132)@+4608|Wg@+8832]
#define W2   16896    // 16896: WkN[j][c](132) -> WoP[j][oc](132)
#define QR   33792    // 4224:  q[r][132] -> o[r][132] -> T1[r][36]
#define QK   38016    // 16512: x[r][132] -> qk[r][516] -> ctx[r][516] -> o2[r][132]
#define SSA  54528    // 2560:  attn[row][n][4h]
#define GG   57088    // 32 gates
#define SMEM_FLOATS 57120    // 228480 B

__global__ void __launch_bounds__(512, 1) k_fused(
    const float* __restrict__ x,
    const float* __restrict__ nb,
    const float* __restrict__ bv, const float* __restrict__ bo,
    const float* __restrict__ Wg, const float* __restrict__ bg,
    float* __restrict__ out)
{
    extern __shared__ float sm[];
    const int t = threadIdx.x;
    const int lane = t & 31;
    const int w = t >> 5;               // warp 0..15
    const int gid = lane >> 2;          // mma group id (row-ish)
    const int tig = lane & 3;           // thread-in-group (col-ish)
    const long rowBase = (long)blockIdx.x * 32;
    unsigned sb = (unsigned)__cvta_generic_to_shared(sm);

    // ============ phase 0: Wq->W1, Wk->W2 (cp.async); x -> QK ============
    #pragma unroll
    for (int i = t; i < 4096; i += 512)
        cpa16(sb + (W1 + (i>>5)*132 + (i&31)*4)*4, g_WqT + i*4);
    #pragma unroll
    for (int i = t; i < 4096; i += 512)
        cpa16(sb + (W2 + (i>>5)*132 + (i&31)*4)*4, g_WkN + i*4);
    cp_commit();
    {
        const float4* xg = (const float4*)x + rowBase*32;
        #pragma unroll
        for (int it = 0; it < 2; it++) {
            int idx = t + 512*it;
            int r = idx >> 5, c4 = idx & 31;
            *(float4*)&sm[QK + r*132 + c4*4] = xg[idx];
        }
    }
    cp_waitall();
    __syncthreads();

    // ============ stage A (mma): q = s*(Wq x + bq) -> QR[r][132] ============
    {
        const int mt = w & 1, ng = w >> 1;
        const int r0 = mt * 16;
        float acc[2][4];
        #pragma unroll
        for (int nt = 0; nt < 2; nt++)
            #pragma unroll
            for (int p = 0; p < 4; p++) acc[nt][p] = 0.0f;
        #pragma unroll 4
        for (int kk = 0; kk < 16; kk++) {
            const int c0 = kk*8;
            unsigned a[4];
            a[0] = f2tf(sm[QK + (r0+gid  )*132 + c0 + tig]);
            a[1] = f2tf(sm[QK + (r0+gid+8)*132 + c0 + tig]);
            a[2] = f2tf(sm[QK + (r0+gid  )*132 + c0 + tig + 4]);
            a[3] = f2tf(sm[QK + (r0+gid+8)*132 + c0 + tig + 4]);
            #pragma unroll
            for (int nt = 0; nt < 2; nt++) {
                const int n0 = ng*16 + nt*8;
                unsigned b0 = __float_as_uint(sm[W1 + (c0+tig  )*132 + n0 + gid]);
                unsigned b1 = __float_as_uint(sm[W1 + (c0+tig+4)*132 + n0 + gid]);
                mma8(acc[nt], a, b0, b1);
            }
        }
        #pragma unroll
        for (int nt = 0; nt < 2; nt++) {
            const int n0 = ng*16 + nt*8;
            float bj0 = __ldg(&g_bqs[n0 + 2*tig]);
            float bj1 = __ldg(&g_bqs[n0 + 2*tig + 1]);
            const int base = QR + (r0+gid)*132 + n0 + 2*tig;
            *(u64*)&sm[base]         = pk2(acc[nt][0]+bj0, acc[nt][1]+bj1);
            *(u64*)&sm[base + 8*132] = pk2(acc[nt][2]+bj0, acc[nt][3]+bj1);
        }
    }
    __syncthreads();
    // W1 free -> prefetch WvT
    #pragma unroll
    for (int i = t; i < 4096; i += 512)
        cpa16(sb + (W1 + (i>>5)*132 + (i&31)*4)*4, g_WvT + i*4);
    cp_commit();

    // ============ stage B (mma): qk[r][h*128+c] -> QK[r][516] (over x) ============
    {
        const int h = w & 3, mt = (w>>2)&1, ng = w>>3;
        const int r0 = mt * 16;
        float acc[8][4];
        #pragma unroll
        for (int i = 0; i < 8; i++)
            #pragma unroll
            for (int p = 0; p < 4; p++) acc[i][p] = 0.0f;
        #pragma unroll
        for (int kk = 0; kk < 4; kk++) {
            const int jc = h*32 + kk*8;
            unsigned a[4];
            a[0] = f2tf(sm[QR + (r0+gid  )*132 + jc + tig]);
            a[1] = f2tf(sm[QR + (r0+gid+8)*132 + jc + tig]);
            a[2] = f2tf(sm[QR + (r0+gid  )*132 + jc + tig + 4]);
            a[3] = f2tf(sm[QR + (r0+gid+8)*132 + jc + tig + 4]);
            #pragma unroll
            for (int i = 0; i < 8; i++) {
                const int n0 = ng*64 + i*8;
                unsigned b0 = __float_as_uint(sm[W2 + (jc+tig  )*132 + n0 + gid]);
                unsigned b1 = __float_as_uint(sm[W2 + (jc+tig+4)*132 + n0 + gid]);
                mma8(acc[i], a, b0, b1);
            }
        }
        // x in QK is dead only after ALL warps finished stage A reads — the
        // post-A barrier above guarantees that. Store qk now.
        #pragma unroll
        for (int i = 0; i < 8; i++) {
            const int n0 = ng*64 + i*8;
            const int base = QK + (r0+gid)*516 + h*128 + n0 + 2*tig;
            *(u64*)&sm[base]         = pk2(acc[i][0], acc[i][1]);
            *(u64*)&sm[base + 8*516] = pk2(acc[i][2], acc[i][3]);
        }
    }
    __syncthreads();
    // W2 free -> prefetch WoP
    #pragma unroll
    for (int i = t; i < 4096; i += 512)
        cpa16(sb + (W2 + (i>>5)*132 + (i&31)*4)*4, g_WoP + i*4);
    cp_commit();

    // ============ stage C1+C2: scores + softmax, warp-per-row (exact fp32) ============
    #pragma unroll
    for (int pass = 0; pass < 2; pass++) {
        const int row = w + pass*16;
        const int n = (lane < 20) ? lane : 19;
        const float* nbr = nb + (((rowBase + row)*20 + n) << 7);
        const float* qkr = sm + QK + row*516;
        u64 acc[4][2];
        #pragma unroll
        for (int h = 0; h < 4; h++) { acc[h][0] = 0ull; acc[h][1] = 0ull; }
        #pragma unroll 4
        for (int c4 = 0; c4 < 32; c4++) {
            float4 v = *(const float4*)(nbr + c4*4);
            u64 v01 = pk2(v.x, v.y), v23 = pk2(v.z, v.w);
            #pragma unroll
            for (int h = 0; h < 4; h++) {
                float4 qv = *(const float4*)(qkr + h*128 + c4*4);
                acc[h][0] = fma2(pk2(qv.x, qv.y), v01, acc[h][0]);
                acc[h][1] = fma2(pk2(qv.z, qv.w), v23, acc[h][1]);
            }
        }
        float sc[4];
        #pragma unroll
        for (int h = 0; h < 4; h++) {
            u64 s2 = add2(acc[h][0], acc[h][1]);
            float lo, hi; upk(s2, lo, hi);
            sc[h] = (lane < 20) ? (lo + hi) : -1e30f;
        }
        float m[4];
        #pragma unroll
        for (int h = 0; h < 4; h++) m[h] = sc[h];
        #pragma unroll
        for (int o = 16; o; o >>= 1) {
            #pragma unroll
            for (int h = 0; h < 4; h++)
                m[h] = fmaxf(m[h], __shfl_xor_sync(0xffffffffu, m[h], o));
        }
        float e[4], s[4];
        #pragma unroll
        for (int h = 0; h < 4; h++) { e[h] = __expf(sc[h] - m[h]); s[h] = e[h]; }
        #pragma unroll
        for (int o = 16; o; o >>= 1) {
            #pragma unroll
            for (int h = 0; h < 4; h++)
                s[h] += __shfl_xor_sync(0xffffffffu, s[h], o);
        }
        if (lane < 20)
            *(float4*)&sm[SSA + row*80 + lane*4] =
                make_float4(e[0]/s[0], e[1]/s[1], e[2]/s[2], e[3]/s[3]);
    }
    __syncthreads();

    // ============ stage C3: ctx[r][h*128+c] -> QK (over qk) ============
    {
        const int cq = w & 3, rq3 = w >> 2;
        const int c = cq*32 + lane;
        u64 cacc[8][2];
        #pragma unroll
        for (int r = 0; r < 8; r++) { cacc[r][0] = 0ull; cacc[r][1] = 0ull; }
        #pragma unroll
        for (int r = 0; r < 8; r++) {
            const int row = rq3*8 + r;
            const float* nbr = nb + ((rowBase + row)*20 << 7) + c;
            #pragma unroll 4
            for (int n = 0; n < 20; n++) {
                float v = __ldg(nbr + n*128);
                u64 vp = pk2(v, v);
                float4 at = *(const float4*)&sm[SSA + row*80 + n*4];
                cacc[r][0] = fma2(pk2(at.x, at.y), vp, cacc[r][0]);
                cacc[r][1] = fma2(pk2(at.z, at.w), vp, cacc[r][1]);
            }
        }
        // qk fully consumed (C1 ended at the barrier above): store ctx
        #pragma unroll
        for (int r = 0; r < 8; r++) {
            const int row = rq3*8 + r;
            float v0, v1, v2, v3;
            upk(cacc[r][0], v0, v1);
            upk(cacc[r][1], v2, v3);
            sm[QK + row*516 +   0 + c] = v0;
            sm[QK + row*516 + 128 + c] = v1;
            sm[QK + row*516 + 256 + c] = v2;
            sm[QK + row*516 + 384 + c] = v3;
        }
    }
    cp_waitall();          // WvT / WoP landed
    __syncthreads();

    // ============ stage D (mma): o = Wv ctx + bv -> QR[r][132] (over q) ============
    {
        const int h = w & 3, mt = (w>>2)&1, ng = w>>3;
        const int r0 = mt * 16;
        float acc[2][4];
        #pragma unroll
        for (int nt = 0; nt < 2; nt++)
            #pragma unroll
            for (int p = 0; p < 4; p++) acc[nt][p] = 0.0f;
        #pragma unroll 4
        for (int kk = 0; kk < 16; kk++) {
            const int c0 = kk*8;
            unsigned a[4];
            a[0] = f2tf(sm[QK + (r0+gid  )*516 + h*128 + c0 + tig]);
            a[1] = f2tf(sm[QK + (r0+gid+8)*516 + h*128 + c0 + tig]);
            a[2] = f2tf(sm[QK + (r0+gid  )*516 + h*128 + c0 + tig + 4]);
            a[3] = f2tf(sm[QK + (r0+gid+8)*516 + h*128 + c0 + tig + 4]);
            #pragma unroll
            for (int nt = 0; nt < 2; nt++) {
                const int jg = h*32 + ng*16 + nt*8;     // global j
                unsigned b0 = __float_as_uint(sm[W1 + (c0+tig  )*132 + jg + gid]);
                unsigned b1 = __float_as_uint(sm[W1 + (c0+tig+4)*132 + jg + gid]);
                mma8(acc[nt], a, b0, b1);
            }
        }
        #pragma unroll
        for (int nt = 0; nt < 2; nt++) {
            const int jg = h*32 + ng*16 + nt*8 + 2*tig;
            float bj0 = __ldg(&bv[jg]), bj1 = __ldg(&bv[jg+1]);
            const int base = QR + (r0+gid)*132 + jg;
            *(u64*)&sm[base]         = pk2(acc[nt][0]+bj0, acc[nt][1]+bj1);
            *(u64*)&sm[base + 8*132] = pk2(acc[nt][2]+bj0, acc[nt][3]+bj1);
        }
    }
    __syncthreads();
    // W1 free -> prefetch SE weights + Wg
    #pragma unroll
    for (int i = t; i < 1024; i += 512)
        cpa16(sb + (W1 + (i>>3)*36 + (i&7)*4)*4, g_Se1T + i*4);
    #pragma unroll
    for (int i = t; i < 1024; i += 512)
        cpa16(sb + (W1 + 4608 + (i>>5)*132 + (i&31)*4)*4, g_Se2T + i*4);
    if (t < 64) cpa16(sb + (W1 + 8832 + t*4)*4, Wg + t*4);
    cp_commit();

    // ============ stage E (mma): o2 = WoP o + bo -> QK[r][132] (over ctx) ============
    {
        const int mt = w & 1, ng = w >> 1;
        const int r0 = mt * 16;
        float acc[2][4];
        #pragma unroll
        for (int nt = 0; nt < 2; nt++)
            #pragma unroll
            for (int p = 0; p < 4; p++) acc[nt][p] = 0.0f;
        #pragma unroll 4
        for (int kk = 0; kk < 16; kk++) {
            const int j0 = kk*8;
            unsigned a[4];
            a[0] = f2tf(sm[QR + (r0+gid  )*132 + j0 + tig]);
            a[1] = f2tf(sm[QR + (r0+gid+8)*132 + j0 + tig]);
            a[2] = f2tf(sm[QR + (r0+gid  )*132 + j0 + tig + 4]);
            a[3] = f2tf(sm[QR + (r0+gid+8)*132 + j0 + tig + 4]);
            #pragma unroll
            for (int nt = 0; nt < 2; nt++) {
                const int n0 = ng*16 + nt*8;
                unsigned b0 = __float_as_uint(sm[W2 + (j0+tig  )*132 + n0 + gid]);
                unsigned b1 = __float_as_uint(sm[W2 + (j0+tig+4)*132 + n0 + gid]);
                mma8(acc[nt], a, b0, b1);
            }
        }
        // ctx fully consumed by all warps (post-D barrier) -> store o2 over it
        #pragma unroll
        for (int nt = 0; nt < 2; nt++) {
            const int oc = ng*16 + nt*8 + 2*tig;
            float bj0 = __ldg(&bo[oc]), bj1 = __ldg(&bo[oc+1]);
            const int base = QK + (r0+gid)*132 + oc;
            *(u64*)&sm[base]         = pk2(acc[nt][0]+bj0, acc[nt][1]+bj1);
            *(u64*)&sm[base + 8*132] = pk2(acc[nt][2]+bj0, acc[nt][3]+bj1);
        }
    }
    cp_waitall();          // SE weights landed
    __syncthreads();

    // ============ stage F (mma, 8 warps): T1 = relu(Se1 . o2) -> QR[r][36] ============
    if (w < 8) {
        const int mt = w & 1, nt = w >> 1;       // 4 n-tiles of 8
        const int r0 = mt * 16;
        const int n0 = nt * 8;
        float acc[4] = {0.f, 0.f, 0.f, 0.f};
        #pragma unroll 4
        for (int kk = 0; kk < 16; kk++) {
            const int k0 = kk*8;
            unsigned a[4];
            a[0] = f2tf(sm[QK + (r0+gid  )*132 + k0 + tig]);
            a[1] = f2tf(sm[QK + (r0+gid+8)*132 + k0 + tig]);
            a[2] = f2tf(sm[QK + (r0+gid  )*132 + k0 + tig + 4]);
            a[3] = f2tf(sm[QK + (r0+gid+8)*132 + k0 + tig + 4]);
            unsigned b0 = __float_as_uint(sm[W1 + (k0+tig  )*36 + n0 + gid]);
            unsigned b1 = __float_as_uint(sm[W1 + (k0+tig+4)*36 + n0 + gid]);
            mma8(acc, a, b0, b1);
        }
        const int base = QR + (r0+gid)*36 + n0 + 2*tig;
        *(u64*)&sm[base]        = pk2(fmaxf(acc[0],0.f), fmaxf(acc[1],0.f));
        *(u64*)&sm[base + 8*36] = pk2(fmaxf(acc[2],0.f), fmaxf(acc[3],0.f));
    }
    __syncthreads();

    // ============ stage G (mma): o2 *= sigmoid(Se2 . T1) in place ============
    {
        const int mt = w & 1, ng = w >> 1;
        const int r0 = mt * 16;
        float acc[2][4];
        #pragma unroll
        for (int nt = 0; nt < 2; nt++)
            #pragma unroll
            for (int p = 0; p < 4; p++) acc[nt][p] = 0.0f;
        #pragma unroll
        for (int kk = 0; kk < 4; kk++) {
            const int i0 = kk*8;
            unsigned a[4];
            a[0] = f2tf(sm[QR + (r0+gid  )*36 + i0 + tig]);
            a[1] = f2tf(sm[QR + (r0+gid+8)*36 + i0 + tig]);
            a[2] = f2tf(sm[QR + (r0+gid  )*36 + i0 + tig + 4]);
            a[3] = f2tf(sm[QR + (r0+gid+8)*36 + i0 + tig + 4]);
            #pragma unroll
            for (int nt = 0; nt < 2; nt++) {
                const int n0 = ng*16 + nt*8;
                unsigned b0 = __float_as_uint(sm[W1 + 4608 + (i0+tig  )*132 + n0 + gid]);
                unsigned b1 = __float_as_uint(sm[W1 + 4608 + (i0+tig+4)*132 + n0 + gid]);
                mma8(acc[nt], a, b0, b1);
            }
        }
        #pragma unroll
        for (int nt = 0; nt < 2; nt++) {
            const int oc = ng*16 + nt*8 + 2*tig;
            const int b0a = QK + (r0+gid)*132 + oc;
            const int b1a = b0a + 8*132;
            float lo, hi;
            u64 v = *(const u64*)&sm[b0a]; upk(v, lo, hi);
            *(u64*)&sm[b0a] = pk2(lo * sigm(acc[nt][0]), hi * sigm(acc[nt][1]));
            v = *(const u64*)&sm[b1a]; upk(v, lo, hi);
            *(u64*)&sm[b1a] = pk2(lo * sigm(acc[nt][2]), hi * sigm(acc[nt][3]));
        }
    }
    __syncthreads();

    // ============ stage H: residual gate (x from L2-hot gmem) ============
    {
        const float bgv = __ldg(bg);
        #pragma unroll
        for (int r2 = 0; r2 < 2; r2++) {
            const int row = 2*w + r2;
            const float* xr = x + (rowBase + row)*128;
            float p = 0.0f;
            #pragma unroll
            for (int k = 0; k < 4; k++) {
                const int cx = lane + 32*k;
                p += sm[W1 + 8832 + cx]       * __ldg(xr + cx);
                p += sm[W1 + 8832 + 128 + cx] * sm[QK + row*132 + cx];
            }
            #pragma unroll
            for (int o = 16; o; o >>= 1) p += __shfl_xor_sync(0xffffffffu, p, o);
            if (lane == 0) sm[GG + row] = sigm(p + bgv);
        }
    }
    __syncthreads();

    // ============ stage I: out = g*o3 + (1-g)*x ============
    {
        const float4* xg = (const float4*)x + rowBase*32;
        float4* og4 = (float4*)out + rowBase*32;
        #pragma unroll
        for (int it = 0; it < 2; it++) {
            const int idx = t + 512*it;
            const int r = idx >> 5, c4 = idx & 31;
            const float g = sm[GG + r];
            float4 xv = __ldg(&xg[idx]);
            float4 ov = *(const float4*)&sm[QK + r*132 + c4*4];
            float4 res;
            res.x = g*ov.x + (1.0f-g)*xv.x;
            res.y = g*ov.y + (1.0f-g)*xv.y;
            res.z = g*ov.z + (1.0f-g)*xv.z;
            res.w = g*ov.w + (1.0f-g)*xv.w;
            og4[idx] = res;
        }
    }
}

// =======================================================================
extern "C" void kernel_launch(void* const* d_in, const int* in_sizes, int n_in,
                              void* d_out, int out_size)
{
    const float* x    = (const float*)d_in[0];
    const float* nb   = (const float*)d_in[1];
    const float* Wq   = (const float*)d_in[2];
    const float* bq   = (const float*)d_in[3];
    const float* Wk   = (const float*)d_in[4];
    // d_in[5] = bk : constant over n => softmax-invariant, unused
    const float* Wv   = (const float*)d_in[6];
    const float* bv   = (const float*)d_in[7];
    const float* Wo   = (const float*)d_in[8];
    const float* bo   = (const float*)d_in[9];
    const float* Wse1 = (const float*)d_in[10];
    const float* Wse2 = (const float*)d_in[11];
    const float* Wg   = (const float*)d_in[12];
    const float* bg   = (const float*)d_in[13];
    float* out = (float*)d_out;

    cudaFuncSetAttribute(k_fused, cudaFuncAttributeMaxDynamicSharedMemorySize,
                         SMEM_FLOATS * 4);

    k_pre<<<64, 256>>>(Wq, bq, Wk, Wv, Wo, Wse1, Wse2);
    k_fused<<<2048, 512, SMEM_FLOATS * 4>>>(x, nb, bv, bo, Wg, bg, out);
}

// round 14
// speedup vs baseline: 1.3902x; 1.0145x over previous
#include <cuda_runtime.h>
#include <math.h>

typedef unsigned long long u64;

// ---------------- pretransposed tf32 weights (device scratch) ----------------
__device__ float g_WqT[16384];   // [c][j]  = tf32(Wq[j][c] * 1/sqrt(32))
__device__ float g_WkN[16384];   // [j][c]  = tf32(Wk[j][c])
__device__ float g_WvT[16384];   // [c][j]  = tf32(Wv[j][c])
__device__ float g_WoP[16384];   // [j][oc] = tf32(Wo[oc][(j&31)*4 + (j>>5)])
__device__ float g_Se1T[4096];   // [oc][i] = tf32(Wse1[i][oc])
__device__ float g_Se2T[4096];   // [i][oc] = tf32(Wse2[oc][i])
__device__ float g_bqs[128];     // bq * 1/sqrt(32)  (fp32 exact)

#define SCALE 0.17677669529663687f

__device__ __forceinline__ unsigned f2tf(float f) {
    unsigned r; asm("cvt.rna.tf32.f32 %0, %1;" : "=r"(r) : "f"(f)); return r;
}

__global__ void k_pre(const float* __restrict__ Wq, const float* __restrict__ bq,
                      const float* __restrict__ Wk,
                      const float* __restrict__ Wv, const float* __restrict__ Wo,
                      const float* __restrict__ Wse1, const float* __restrict__ Wse2)
{
    int i = blockIdx.x * 256 + threadIdx.x;
    if (i < 16384) {
        int a = i >> 7, b = i & 127;
        g_WqT[i] = __uint_as_float(f2tf(Wq[b*128 + a] * SCALE));
        g_WkN[i] = __uint_as_float(f2tf(Wk[i]));
        g_WvT[i] = __uint_as_float(f2tf(Wv[b*128 + a]));
        int j = a, oc = b;
        g_WoP[i] = __uint_as_float(f2tf(Wo[oc*128 + ((j & 31)*4 + (j >> 5))]));
    }
    if (i < 4096) {
        int oc1 = i >> 5, i1 = i & 31;
        g_Se1T[i] = __uint_as_float(f2tf(Wse1[i1*128 + oc1]));
        int i2 = i >> 7, oc2 = i & 127;
        g_Se2T[i] = __uint_as_float(f2tf(Wse2[oc2*32 + i2]));
    }
    if (i < 128) g_bqs[i] = bq[i] * SCALE;
}

// ---------------- helpers ----------------
__device__ __forceinline__ u64 pk2(float lo, float hi) {
    u64 r; asm("mov.b64 %0, {%1, %2};" : "=l"(r) : "f"(lo), "f"(hi)); return r;
}
__device__ __forceinline__ void upk(u64 v, float& lo, float& hi) {
    asm("mov.b64 {%0, %1}, %2;" : "=f"(lo), "=f"(hi) : "l"(v));
}
__device__ __forceinline__ u64 fma2(u64 a, u64 b, u64 c) {
    u64 d; asm("fma.rn.f32x2 %0, %1, %2, %3;" : "=l"(d) : "l"(a), "l"(b), "l"(c)); return d;
}
__device__ __forceinline__ u64 add2(u64 a, u64 b) {
    u64 d; asm("add.rn.f32x2 %0, %1, %2;" : "=l"(d) : "l"(a), "l"(b)); return d;
}
__device__ __forceinline__ void mma8(float d[4], const unsigned a[4],
                                     unsigned b0, unsigned b1) {
    asm volatile(
        "mma.sync.aligned.m16n8k8.row.col.f32.tf32.tf32.f32 "
        "{%0,%1,%2,%3}, {%4,%5,%6,%7}, {%8,%9}, {%0,%1,%2,%3};"
        : "+f"(d[0]), "+f"(d[1]), "+f"(d[2]), "+f"(d[3])
        : "r"(a[0]), "r"(a[1]), "r"(a[2]), "r"(a[3]), "r"(b0), "r"(b1));
}
__device__ __forceinline__ void cpa16(unsigned dst, const void* src) {
    asm volatile("cp.async.cg.shared.global [%0], [%1], 16;" :: "r"(dst), "l"(src));
}
__device__ __forceinline__ void cp_commit() { asm volatile("cp.async.commit_group;"); }
__device__ __forceinline__ void cp_waitall() { asm volatile("cp.async.wait_group 0;" ::: "memory"); }
__device__ __forceinline__ float sigm(float z) { return 1.0f / (1.0f + __expf(-z)); }

// ---------------- smem layout (floats), 32 rows/block, 1024 threads ----------------
// Weight buffers padded to 136 (B-frag bank-conflict-free: (tig*8+gid)%32 distinct)
#define W1   0        // 17408: WqT[c][j](136) -> WvT(136) -> [Se1T(40) | Se2T(136)@+5120 | Wg@+9472]
#define W2   17408    // 17408: WkN[j][c](136) -> WoP[j][oc](136)
#define QR   34816    // 4224:  q[r][132] -> attn[row][80] -> o[r][132] -> T1[r][36]; GG@+2560
#define QK   39040    // 16512: x[r][132] -> qk[r][516] -> ctx[r][516] -> o2[r][132]
#define GG   (QR + 2560)
#define SMEM_FLOATS 55552    // 222208 B

__global__ void __launch_bounds__(1024, 1) k_fused(
    const float* __restrict__ x,
    const float* __restrict__ nb,
    const float* __restrict__ bv, const float* __restrict__ bo,
    const float* __restrict__ Wg, const float* __restrict__ bg,
    float* __restrict__ out)
{
    extern __shared__ float sm[];
    const int t = threadIdx.x;
    const int lane = t & 31;
    const int w = t >> 5;               // warp 0..31
    const int gid = lane >> 2;          // mma group id (row-ish)
    const int tig = lane & 3;           // thread-in-group (col-ish)
    const long rowBase = (long)blockIdx.x * 32;
    unsigned sb = (unsigned)__cvta_generic_to_shared(sm);

    // ============ phase 0: Wq->W1, Wk->W2 (cp.async, pad 136); x -> QK ============
    #pragma unroll
    for (int i = t; i < 4096; i += 1024)
        cpa16(sb + (W1 + (i>>5)*136 + (i&31)*4)*4, g_WqT + i*4);
    #pragma unroll
    for (int i = t; i < 4096; i += 1024)
        cpa16(sb + (W2 + (i>>5)*136 + (i&31)*4)*4, g_WkN + i*4);
    cp_commit();
    {
        const float4* xg = (const float4*)x + rowBase*32;
        int r = t >> 5, c4 = t & 31;
        *(float4*)&sm[QK + r*132 + c4*4] = xg[t];
    }
    cp_waitall();
    __syncthreads();

    // ============ stage A (mma): q = s*(Wq x + bq) -> QR[r][132] ============
    {
        const int mt = w & 1, ng = w >> 1;      // ng 0..15
        const int r0 = mt * 16, n0 = ng * 8;
        float acc[4] = {0.f, 0.f, 0.f, 0.f};
        #pragma unroll 4
        for (int kk = 0; kk < 16; kk++) {
            const int c0 = kk*8;
            unsigned a[4];
            a[0] = f2tf(sm[QK + (r0+gid  )*132 + c0 + tig]);
            a[1] = f2tf(sm[QK + (r0+gid+8)*132 + c0 + tig]);
            a[2] = f2tf(sm[QK + (r0+gid  )*132 + c0 + tig + 4]);
            a[3] = f2tf(sm[QK + (r0+gid+8)*132 + c0 + tig + 4]);
            unsigned b0 = __float_as_uint(sm[W1 + (c0+tig  )*136 + n0 + gid]);
            unsigned b1 = __float_as_uint(sm[W1 + (c0+tig+4)*136 + n0 + gid]);
            mma8(acc, a, b0, b1);
        }
        float bj0 = __ldg(&g_bqs[n0 + 2*tig]);
        float bj1 = __ldg(&g_bqs[n0 + 2*tig + 1]);
        const int base = QR + (r0+gid)*132 + n0 + 2*tig;
        *(u64*)&sm[base]         = pk2(acc[0]+bj0, acc[1]+bj1);
        *(u64*)&sm[base + 8*132] = pk2(acc[2]+bj0, acc[3]+bj1);
    }
    __syncthreads();
    // W1 free -> prefetch WvT
    #pragma unroll
    for (int i = t; i < 4096; i += 1024)
        cpa16(sb + (W1 + (i>>5)*136 + (i&31)*4)*4, g_WvT + i*4);
    cp_commit();

    // ============ stage B (mma): qk[r][512] -> QK (over x) ============
    // Output col global = nb0 + i*8 (0..511); Wk col is HEAD-LOCAL: cl0 + i*8 (0..127).
    {
        const int mt = w & 1, ng = w >> 1;      // ng 0..15 -> 32 qk-cols each
        const int r0 = mt * 16;
        const int h = ng >> 2;                  // head
        const int nb0 = ng * 32;                // global qk col base
        const int cl0 = (ng & 3) * 32;          // head-local Wk col base
        float acc[4][4];
        #pragma unroll
        for (int i = 0; i < 4; i++)
            #pragma unroll
            for (int p = 0; p < 4; p++) acc[i][p] = 0.0f;
        #pragma unroll
        for (int kk = 0; kk < 4; kk++) {
            const int jc = h*32 + kk*8;
            unsigned a[4];
            a[0] = f2tf(sm[QR + (r0+gid  )*132 + jc + tig]);
            a[1] = f2tf(sm[QR + (r0+gid+8)*132 + jc + tig]);
            a[2] = f2tf(sm[QR + (r0+gid  )*132 + jc + tig + 4]);
            a[3] = f2tf(sm[QR + (r0+gid+8)*132 + jc + tig + 4]);
            #pragma unroll
            for (int i = 0; i < 4; i++) {
                const int cl = cl0 + i*8;       // head-local column into Wk
                unsigned b0 = __float_as_uint(sm[W2 + (jc+tig  )*136 + cl + gid]);
                unsigned b1 = __float_as_uint(sm[W2 + (jc+tig+4)*136 + cl + gid]);
                mma8(acc[i], a, b0, b1);
            }
        }
        __syncthreads();     // all stage-A/B reads of QK(x)/QR(q) complete
        #pragma unroll
        for (int i = 0; i < 4; i++) {
            const int base = QK + (r0+gid)*516 + nb0 + i*8 + 2*tig;
            *(u64*)&sm[base]         = pk2(acc[i][0], acc[i][1]);
            *(u64*)&sm[base + 8*516] = pk2(acc[i][2], acc[i][3]);
        }
    }
    __syncthreads();
    // W2 free -> prefetch WoP
    #pragma unroll
    for (int i = t; i < 4096; i += 1024)
        cpa16(sb + (W2 + (i>>5)*136 + (i&31)*4)*4, g_WoP + i*4);
    cp_commit();

    // ============ stage C1+C2: scores + softmax (warp = row, exact fp32) ============
    // attn written to QR region (q dead after B; post-B barrier passed). Rows warp-private.
    {
        const int row = w;
        const int n = (lane < 20) ? lane : 19;
        const float* nbr = nb + (((rowBase + row)*20 + n) << 7);
        const float* qkr = sm + QK + row*516;
        u64 acc[4][2];
        #pragma unroll
        for (int h = 0; h < 4; h++) { acc[h][0] = 0ull; acc[h][1] = 0ull; }
        #pragma unroll 4
        for (int c4 = 0; c4 < 32; c4++) {
            float4 v = *(const float4*)(nbr + c4*4);
            u64 v01 = pk2(v.x, v.y), v23 = pk2(v.z, v.w);
            #pragma unroll
            for (int h = 0; h < 4; h++) {
                float4 qv = *(const float4*)(qkr + h*128 + c4*4);
                acc[h][0] = fma2(pk2(qv.x, qv.y), v01, acc[h][0]);
                acc[h][1] = fma2(pk2(qv.z, qv.w), v23, acc[h][1]);
            }
        }
        float sc[4];
        #pragma unroll
        for (int h = 0; h < 4; h++) {
            u64 s2 = add2(acc[h][0], acc[h][1]);
            float lo, hi; upk(s2, lo, hi);
            sc[h] = (lane < 20) ? (lo + hi) : -1e30f;
        }
        float m[4];
        #pragma unroll
        for (int h = 0; h < 4; h++) m[h] = sc[h];
        #pragma unroll
        for (int o = 16; o; o >>= 1) {
            #pragma unroll
            for (int h = 0; h < 4; h++)
                m[h] = fmaxf(m[h], __shfl_xor_sync(0xffffffffu, m[h], o));
        }
        float e[4], s[4];
        #pragma unroll
        for (int h = 0; h < 4; h++) { e[h] = __expf(sc[h] - m[h]); s[h] = e[h]; }
        #pragma unroll
        for (int o = 16; o; o >>= 1) {
            #pragma unroll
            for (int h = 0; h < 4; h++)
                s[h] += __shfl_xor_sync(0xffffffffu, s[h], o);
        }
        if (lane < 20)
            *(float4*)&sm[QR + row*80 + lane*4] =
                make_float4(e[0]/s[0], e[1]/s[1], e[2]/s[2], e[3]/s[3]);
    }
    __syncwarp();

    // ============ stage C3: ctx[r][512] -> QK (over qk; row warp-private) ============
    {
        const int row = w;
        const float* nbr = nb + ((rowBase + row)*20 << 7);
        u64 acc[4][2];
        #pragma unroll
        for (int ch = 0; ch < 4; ch++) { acc[ch][0] = 0ull; acc[ch][1] = 0ull; }
        #pragma unroll 4
        for (int n = 0; n < 20; n++) {
            float4 at = *(const float4*)&sm[QR + row*80 + n*4];   // broadcast
            u64 a01 = pk2(at.x, at.y), a23 = pk2(at.z, at.w);
            #pragma unroll
            for (int ch = 0; ch < 4; ch++) {
                float v = __ldg(nbr + n*128 + ch*32 + lane);
                u64 vp = pk2(v, v);
                acc[ch][0] = fma2(a01, vp, acc[ch][0]);
                acc[ch][1] = fma2(a23, vp, acc[ch][1]);
            }
        }
        #pragma unroll
        for (int ch = 0; ch < 4; ch++) {
            const int c = ch*32 + lane;
            float v0, v1, v2, v3;
            upk(acc[ch][0], v0, v1);
            upk(acc[ch][1], v2, v3);
            sm[QK + row*516 +   0 + c] = v0;
            sm[QK + row*516 + 128 + c] = v1;
            sm[QK + row*516 + 256 + c] = v2;
            sm[QK + row*516 + 384 + c] = v3;
        }
    }
    cp_waitall();          // WvT / WoP landed
    __syncthreads();

    // ============ stage D (mma): o = Wv ctx + bv -> QR[r][132] ============
    {
        const int mt = w & 1, nt = w >> 1;      // nt 0..15
        const int r0 = mt * 16, n0 = nt * 8;    // n0 = global j (Wv output)
        const int h = nt >> 2;                  // head of output j-range
        float acc[4] = {0.f, 0.f, 0.f, 0.f};
        #pragma unroll 4
        for (int kk = 0; kk < 16; kk++) {
            const int c0 = kk*8;
            unsigned a[4];
            a[0] = f2tf(sm[QK + (r0+gid  )*516 + h*128 + c0 + tig]);
            a[1] = f2tf(sm[QK + (r0+gid+8)*516 + h*128 + c0 + tig]);
            a[2] = f2tf(sm[QK + (r0+gid  )*516 + h*128 + c0 + tig + 4]);
            a[3] = f2tf(sm[QK + (r0+gid+8)*516 + h*128 + c0 + tig + 4]);
            unsigned b0 = __float_as_uint(sm[W1 + (c0+tig  )*136 + n0 + gid]);
            unsigned b1 = __float_as_uint(sm[W1 + (c0+tig+4)*136 + n0 + gid]);
            mma8(acc, a, b0, b1);
        }
        float bj0 = __ldg(&bv[n0 + 2*tig]);
        float bj1 = __ldg(&bv[n0 + 2*tig + 1]);
        const int base = QR + (r0+gid)*132 + n0 + 2*tig;
        *(u64*)&sm[base]         = pk2(acc[0]+bj0, acc[1]+bj1);
        *(u64*)&sm[base + 8*132] = pk2(acc[2]+bj0, acc[3]+bj1);
    }
    __syncthreads();
    // W1 free -> prefetch SE weights + Wg
    #pragma unroll
    for (int i = t; i < 1024; i += 1024)
        cpa16(sb + (W1 + (i>>3)*40 + (i&7)*4)*4, g_Se1T + i*4);
    #pragma unroll
    for (int i = t; i < 1024; i += 1024)
        cpa16(sb + (W1 + 5120 + (i>>5)*136 + (i&31)*4)*4, g_Se2T + i*4);
    if (t < 64) cpa16(sb + (W1 + 9472 + t*4)*4, Wg + t*4);
    cp_commit();

    // ============ stage E (mma): o2 = WoP o + bo -> QK[r][132] (over ctx) ============
    {
        const int mt = w & 1, nt = w >> 1;
        const int r0 = mt * 16, n0 = nt * 8;
        float acc[4] = {0.f, 0.f, 0.f, 0.f};
        #pragma unroll 4
        for (int kk = 0; kk < 16; kk++) {
            const int j0 = kk*8;
            unsigned a[4];
            a[0] = f2tf(sm[QR + (r0+gid  )*132 + j0 + tig]);
            a[1] = f2tf(sm[QR + (r0+gid+8)*132 + j0 + tig]);
            a[2] = f2tf(sm[QR + (r0+gid  )*132 + j0 + tig + 4]);
            a[3] = f2tf(sm[QR + (r0+gid+8)*132 + j0 + tig + 4]);
            unsigned b0 = __float_as_uint(sm[W2 + (j0+tig  )*136 + n0 + gid]);
            unsigned b1 = __float_as_uint(sm[W2 + (j0+tig+4)*136 + n0 + gid]);
            mma8(acc, a, b0, b1);
        }
        __syncthreads();     // all E reads of ctx (QK) done before o2 overwrites
        float bj0 = __ldg(&bo[n0 + 2*tig]);
        float bj1 = __ldg(&bo[n0 + 2*tig + 1]);
        const int base = QK + (r0+gid)*132 + n0 + 2*tig;
        *(u64*)&sm[base]         = pk2(acc[0]+bj0, acc[1]+bj1);
        *(u64*)&sm[base + 8*132] = pk2(acc[2]+bj0, acc[3]+bj1);
    }
    cp_waitall();          // SE weights landed
    __syncthreads();

    // ============ stage F (mma, 8 warps): T1 = relu(Se1 . o2) -> QR[r][36] ============
    if (w < 8) {
        const int mt = w & 1, nt = w >> 1;      // nt 0..3
        const int r0 = mt * 16, n0 = nt * 8;
        float acc[4] = {0.f, 0.f, 0.f, 0.f};
        #pragma unroll 4
        for (int kk = 0; kk < 16; kk++) {
            const int k0 = kk*8;
            unsigned a[4];
            a[0] = f2tf(sm[QK + (r0+gid  )*132 + k0 + tig]);
            a[1] = f2tf(sm[QK + (r0+gid+8)*132 + k0 + tig]);
            a[2] = f2tf(sm[QK + (r0+gid  )*132 + k0 + tig + 4]);
            a[3] = f2tf(sm[QK + (r0+gid+8)*132 + k0 + tig + 4]);
            unsigned b0 = __float_as_uint(sm[W1 + (k0+tig  )*40 + n0 + gid]);
            unsigned b1 = __float_as_uint(sm[W1 + (k0+tig+4)*40 + n0 + gid]);
            mma8(acc, a, b0, b1);
        }
        const int base = QR + (r0+gid)*36 + n0 + 2*tig;
        *(u64*)&sm[base]        = pk2(fmaxf(acc[0],0.f), fmaxf(acc[1],0.f));
        *(u64*)&sm[base + 8*36] = pk2(fmaxf(acc[2],0.f), fmaxf(acc[3],0.f));
    }
    __syncthreads();

    // ============ stage G (mma): o2 *= sigmoid(Se2 . T1) in place ============
    {
        const int mt = w & 1, nt = w >> 1;
        const int r0 = mt * 16, n0 = nt * 8;
        float acc[4] = {0.f, 0.f, 0.f, 0.f};
        #pragma unroll
        for (int kk = 0; kk < 4; kk++) {
            const int i0 = kk*8;
            unsigned a[4];
            a[0] = f2tf(sm[QR + (r0+gid  )*36 + i0 + tig]);
            a[1] = f2tf(sm[QR + (r0+gid+8)*36 + i0 + tig]);
            a[2] = f2tf(sm[QR + (r0+gid  )*36 + i0 + tig + 4]);
            a[3] = f2tf(sm[QR + (r0+gid+8)*36 + i0 + tig + 4]);
            unsigned b0 = __float_as_uint(sm[W1 + 5120 + (i0+tig  )*136 + n0 + gid]);
            unsigned b1 = __float_as_uint(sm[W1 + 5120 + (i0+tig+4)*136 + n0 + gid]);
            mma8(acc, a, b0, b1);
        }
        const int b0a = QK + (r0+gid)*132 + n0 + 2*tig;
        const int b1a = b0a + 8*132;
        float lo, hi;
        u64 v = *(const u64*)&sm[b0a]; upk(v, lo, hi);
        *(u64*)&sm[b0a] = pk2(lo * sigm(acc[0]), hi * sigm(acc[1]));
        v = *(const u64*)&sm[b1a]; upk(v, lo, hi);
        *(u64*)&sm[b1a] = pk2(lo * sigm(acc[2]), hi * sigm(acc[3]));
    }
    __syncthreads();

    // ============ stage H: residual gate (warp = row; x from L2-hot gmem) ============
    {
        const float bgv = __ldg(bg);
        const int row = w;
        const float* xr = x + (rowBase + row)*128;
        float p = 0.0f;
        #pragma unroll
        for (int k = 0; k < 4; k++) {
            const int cx = lane + 32*k;
            p += sm[W1 + 9472 + cx]       * __ldg(xr + cx);
            p += sm[W1 + 9472 + 128 + cx] * sm[QK + row*132 + cx];
        }
        #pragma unroll
        for (int o = 16; o; o >>= 1) p += __shfl_xor_sync(0xffffffffu, p, o);
        if (lane == 0) sm[GG + row] = sigm(p + bgv);
    }
    __syncthreads();

    // ============ stage I: out = g*o3 + (1-g)*x ============
    {
        const float4* xg = (const float4*)x + rowBase*32;
        float4* og4 = (float4*)out + rowBase*32;
        const int r = t >> 5, c4 = t & 31;
        const float g = sm[GG + r];
        float4 xv = __ldg(&xg[t]);
        float4 ov = *(const float4*)&sm[QK + r*132 + c4*4];
        float4 res;
        res.x = g*ov.x + (1.0f-g)*xv.x;
        res.y = g*ov.y + (1.0f-g)*xv.y;
        res.z = g*ov.z + (1.0f-g)*xv.z;
        res.w = g*ov.w + (1.0f-g)*xv.w;
        og4[t] = res;
    }
}

// =======================================================================
extern "C" void kernel_launch(void* const* d_in, const int* in_sizes, int n_in,
                              void* d_out, int out_size)
{
    const float* x    = (const float*)d_in[0];
    const float* nb   = (const float*)d_in[1];
    const float* Wq   = (const float*)d_in[2];
    const float* bq   = (const float*)d_in[3];
    const float* Wk   = (const float*)d_in[4];
    // d_in[5] = bk : constant over n => softmax-invariant, unused
    const float* Wv   = (const float*)d_in[6];
    const float* bv   = (const float*)d_in[7];
    const float* Wo   = (const float*)d_in[8];
    const float* bo   = (const float*)d_in[9];
    const float* Wse1 = (const float*)d_in[10];
    const float* Wse2 = (const float*)d_in[11];
    const float* Wg   = (const float*)d_in[12];
    const float* bg   = (const float*)d_in[13];
    float* out = (float*)d_out;

    cudaFuncSetAttribute(k_fused, cudaFuncAttributeMaxDynamicSharedMemorySize,
                         SMEM_FLOATS * 4);

    k_pre<<<64, 256>>>(Wq, bq, Wk, Wv, Wo, Wse1, Wse2);
    k_fused<<<2048, 1024, SMEM_FLOATS * 4>>>(x, nb, bv, bo, Wg, bg, out);
}